// round 2
// baseline (speedup 1.0000x reference)
#include <cuda_runtime.h>
#include <cuda_bf16.h>
#include <math.h>

#define G_CNT 1024
#define A_CNT 20
#define N_CNT (G_CNT * A_CNT)      // 20480
#define E_CNT (G_CNT * A_CNT * A_CNT) // 409600
#define H_DIM 128
#define LAT_DIM 256
#define NLAYER 4

// ---------------- scratch (device globals; no runtime allocation) ----------
__device__ float g_h[N_CNT * H_DIM];        // node features
__device__ float g_hs[N_CNT * H_DIM];       // h @ W1[:128]   (src half)
__device__ float g_hd[N_CNT * H_DIM];       // h @ W1[128:256] (dst half)
__device__ float g_agg[N_CNT * H_DIM];      // scatter-mean of edge features
__device__ float g_latip[G_CNT * 9];        // L @ L^T per graph
__device__ float g_latterm[G_CNT * H_DIM];  // lat_ip @ W1[256:265] + b1
__device__ float g_disT[G_CNT * 60 * 400];  // dis, per-graph transposed [g][k][r]

__device__ __forceinline__ float siluf(float x) {
    return x / (1.0f + __expf(-x));
}

// acc[0..19] += a[0..19] * w, a is 16B-aligned shared pointer
__device__ __forceinline__ void fma20(float acc[20], const float* __restrict__ a, float w) {
#pragma unroll
    for (int q = 0; q < 5; ++q) {
        float4 v = reinterpret_cast<const float4*>(a)[q];
        acc[q * 4 + 0] += v.x * w;
        acc[q * 4 + 1] += v.y * w;
        acc[q * 4 + 2] += v.z * w;
        acc[q * 4 + 3] += v.w * w;
    }
}

// ---------------- lat_ip = L @ L^T ----------------
__global__ void k_latip(const float* __restrict__ lattices) {
    int g = blockIdx.x, tid = threadIdx.x;
    if (tid < 9) {
        int i = tid / 3, k = tid % 3;
        float s = 0.f;
#pragma unroll
        for (int j = 0; j < 3; ++j)
            s += lattices[g * 9 + i * 3 + j] * lattices[g * 9 + k * 3 + j];
        g_latip[g * 9 + tid] = s;
    }
}

// ---------------- dis embedding (one-time, layer-invariant) ----------------
__global__ __launch_bounds__(256) void k_dis(const float* __restrict__ fc) {
    int e = blockIdx.x * 256 + threadIdx.x;
    if (e >= E_CNT) return;
    int g = e / 400;
    int r = e % 400;
    int src = g * 20 + r / 20;
    int dst = g * 20 + r % 20;
    float* base = g_disT + (size_t)g * 24000;
#pragma unroll
    for (int c = 0; c < 3; ++c) {
        float d = fc[dst * 3 + c] - fc[src * 3 + c];
        d -= floorf(d); // python-style mod 1 -> [0,1)
#pragma unroll
        for (int f = 0; f < 10; ++f) {
            float s, co;
            sincospif(2.0f * (float)f * d, &s, &co); // sin/cos(2*pi*f*d), exact reduction
            base[(c * 10 + f) * 400 + r] = s;
            base[(30 + c * 10 + f) * 400 + r] = co;
        }
    }
}

// ---------------- node embedding + latent conditioning ----------------
__global__ __launch_bounds__(128) void k_embed(
    const int* __restrict__ atom_types, const float* __restrict__ t,
    const float* __restrict__ emb_table, const float* __restrict__ w_latent,
    const float* __restrict__ b_latent)
{
    __shared__ __align__(16) float inT[384 * 20];
    __shared__ int at[20];
    int g = blockIdx.x, tid = threadIdx.x;
    if (tid < 20) at[tid] = atom_types[g * 20 + tid];
    __syncthreads();
    // emb rows, transposed [k][n]
    for (int n = 0; n < 20; ++n)
        inT[tid * 20 + n] = emb_table[at[n] * H_DIM + tid];
    // t row broadcast to all 20 nodes
    for (int k = tid; k < 256; k += 128) {
        float v = t[g * 256 + k];
#pragma unroll
        for (int n = 0; n < 20; ++n) inT[(128 + k) * 20 + n] = v;
    }
    __syncthreads();
    int col = tid;
    float acc[20];
    float b = b_latent[col];
#pragma unroll
    for (int j = 0; j < 20; ++j) acc[j] = b;
#pragma unroll 4
    for (int k = 0; k < 384; ++k) {
        float w = w_latent[k * H_DIM + col];
        fma20(acc, &inT[k * 20], w);
    }
#pragma unroll
    for (int j = 0; j < 20; ++j)
        g_h[(g * 20 + j) * H_DIM + col] = acc[j];
}

// ---------------- per-layer node-side precompute: hs, hd, lat_term --------
__global__ __launch_bounds__(128) void k_nodeside(
    const float* __restrict__ ew1, const float* __restrict__ eb1)
{
    __shared__ __align__(16) float hT[128 * 20];
    int g = blockIdx.x, tid = threadIdx.x;
    for (int n = 0; n < 20; ++n)
        hT[tid * 20 + n] = g_h[(g * 20 + n) * H_DIM + tid];
    __syncthreads();
    int col = tid;
    float as[20], ad[20];
#pragma unroll
    for (int j = 0; j < 20; ++j) { as[j] = 0.f; ad[j] = 0.f; }
#pragma unroll 2
    for (int k = 0; k < 128; ++k) {
        float ws = ew1[k * H_DIM + col];
        float wd = ew1[(128 + k) * H_DIM + col];
        const float* a = &hT[k * 20];
        fma20(as, a, ws);
        fma20(ad, a, wd);
    }
#pragma unroll
    for (int j = 0; j < 20; ++j) {
        g_hs[(g * 20 + j) * H_DIM + col] = as[j];
        g_hd[(g * 20 + j) * H_DIM + col] = ad[j];
    }
    float lt = eb1[col];
#pragma unroll
    for (int j = 0; j < 9; ++j)
        lt += g_latip[g * 9 + j] * ew1[(256 + j) * H_DIM + col];
    g_latterm[g * H_DIM + col] = lt;
}

// ---------------- per-layer edge kernel (the big one) ----------------
// block = 1 graph (400 edges), 256 threads, weights resident in smem.
// pass p handles srcs {2p, 2p+1}; thread (ss=tid/128) owns one src's 20 edges
// for one output column (col=tid%128): no cross-thread reduction for the mean.
__global__ __launch_bounds__(256) void k_edge(
    const float* __restrict__ ew1, const float* __restrict__ ew2,
    const float* __restrict__ eb2)
{
    extern __shared__ __align__(16) float sm[];
    float* smW1d = sm;                 // 60*128  = 7680
    float* smW2  = sm + 7680;          // 128*128 = 16384
    float* smB2  = sm + 24064;         // 128
    float* smHs  = sm + 24192;         // 20*128
    float* smHd  = sm + 26752;         // 20*128
    float* smLat = sm + 29312;         // 128
    float* smEf  = sm + 29440;         // 128*40 = 5120
    float* smDis = sm + 34560;         // 60*40  = 2400
    int g = blockIdx.x, tid = threadIdx.x;

    for (int i = tid; i < 7680; i += 256) smW1d[i] = ew1[265 * H_DIM + i];
    for (int i = tid; i < 16384; i += 256) smW2[i] = ew2[i];
    for (int i = tid; i < 2560; i += 256) {
        smHs[i] = g_hs[g * 2560 + i];
        smHd[i] = g_hd[g * 2560 + i];
    }
    if (tid < 128) {
        smB2[tid] = eb2[tid];
        smLat[tid] = g_latterm[g * H_DIM + tid];
    }
    __syncthreads();

    int col = tid & 127;
    int ss = tid >> 7;
    float b2v = smB2[col];
    const float* disG = g_disT + (size_t)g * 24000;

    for (int p = 0; p < 10; ++p) {
        // stage dis for 2 srcs (40 edges x 60 feats), transposed [k][local]
        for (int i = tid; i < 2400; i += 256)
            smDis[i] = disG[(i / 40) * 400 + p * 40 + (i % 40)];
        __syncthreads();

        int s = 2 * p + ss;
        // ---- phase A: pre-activation + first silu (edge MLP layer 1) ----
        float acc[20];
        float hsl = smHs[s * H_DIM + col] + smLat[col];
#pragma unroll
        for (int j = 0; j < 20; ++j) acc[j] = hsl + smHd[j * H_DIM + col];
#pragma unroll 4
        for (int k = 0; k < 60; ++k) {
            float w = smW1d[k * H_DIM + col];
            fma20(acc, &smDis[k * 40 + ss * 20], w);
        }
#pragma unroll
        for (int q = 0; q < 5; ++q) {
            float4 v;
            v.x = siluf(acc[q * 4 + 0]);
            v.y = siluf(acc[q * 4 + 1]);
            v.z = siluf(acc[q * 4 + 2]);
            v.w = siluf(acc[q * 4 + 3]);
            reinterpret_cast<float4*>(&smEf[col * 40 + ss * 20])[q] = v;
        }
        __syncthreads();

        // ---- phase B: ef @ W2 + silu + mean over the 20 edges of src s ----
        float acc2[20];
#pragma unroll
        for (int j = 0; j < 20; ++j) acc2[j] = b2v;
#pragma unroll 4
        for (int k = 0; k < 128; ++k) {
            float w = smW2[k * H_DIM + col];
            fma20(acc2, &smEf[k * 40 + ss * 20], w);
        }
        float ssum = 0.f;
#pragma unroll
        for (int j = 0; j < 20; ++j) ssum += siluf(acc2[j]);
        g_agg[(g * 20 + s) * H_DIM + col] = ssum * 0.05f; // scatter-mean (counts==20)
        __syncthreads();
    }
}

// ---------------- per-layer node MLP + residual ----------------
__global__ __launch_bounds__(128) void k_nodemlp(
    const float* __restrict__ nw1, const float* __restrict__ nb1,
    const float* __restrict__ nw2, const float* __restrict__ nb2)
{
    __shared__ __align__(16) float inT[256 * 20];
    __shared__ __align__(16) float nfT[128 * 20];
    int g = blockIdx.x, tid = threadIdx.x, col = tid;
    for (int n = 0; n < 20; ++n) {
        inT[tid * 20 + n] = g_h[(g * 20 + n) * H_DIM + tid];
        inT[(128 + tid) * 20 + n] = g_agg[(g * 20 + n) * H_DIM + tid];
    }
    __syncthreads();
    float acc[20];
    float b1 = nb1[col];
#pragma unroll
    for (int j = 0; j < 20; ++j) acc[j] = b1;
#pragma unroll 4
    for (int k = 0; k < 256; ++k) {
        float w = nw1[k * H_DIM + col];
        fma20(acc, &inT[k * 20], w);
    }
#pragma unroll
    for (int q = 0; q < 5; ++q) {
        float4 v;
        v.x = siluf(acc[q * 4 + 0]);
        v.y = siluf(acc[q * 4 + 1]);
        v.z = siluf(acc[q * 4 + 2]);
        v.w = siluf(acc[q * 4 + 3]);
        reinterpret_cast<float4*>(&nfT[col * 20])[q] = v;
    }
    __syncthreads();
    float acc2[20];
    float b2 = nb2[col];
#pragma unroll
    for (int j = 0; j < 20; ++j) acc2[j] = b2;
#pragma unroll 4
    for (int k = 0; k < 128; ++k) {
        float w = nw2[k * H_DIM + col];
        fma20(acc2, &nfT[k * 20], w);
    }
#pragma unroll
    for (int j = 0; j < 20; ++j)
        g_h[(g * 20 + j) * H_DIM + col] = inT[col * 20 + j] + siluf(acc2[j]);
}

// ---------------- output heads ----------------
__global__ __launch_bounds__(128) void k_final(
    const float* __restrict__ lattices, const float* __restrict__ coord_w,
    const float* __restrict__ lattice_w, float* __restrict__ out)
{
    __shared__ __align__(16) float hT[128 * 20];
    __shared__ float gf[128];
    __shared__ float pre[9];
    int g = blockIdx.x, tid = threadIdx.x;
    for (int n = 0; n < 20; ++n)
        hT[tid * 20 + n] = g_h[(g * 20 + n) * H_DIM + tid];
    __syncthreads();
    // graph mean
    float s = 0.f;
#pragma unroll
    for (int n = 0; n < 20; ++n) s += hT[tid * 20 + n];
    gf[tid] = s * 0.05f;
    __syncthreads();
    if (tid < 9) {
        float acc = 0.f;
        for (int k = 0; k < 128; ++k) acc += gf[k] * lattice_w[k * 9 + tid];
        pre[tid] = acc;
    }
    __syncthreads();
    if (tid < 9) {
        int i = tid / 3, kk = tid % 3;
        float v = 0.f;
#pragma unroll
        for (int j = 0; j < 3; ++j)
            v += pre[i * 3 + j] * lattices[g * 9 + j * 3 + kk];
        out[g * 9 + tid] = v;
    }
    if (tid < 60) {
        int n = tid / 3, c = tid % 3;
        float acc = 0.f;
        for (int k = 0; k < 128; ++k) acc += hT[k * 20 + n] * coord_w[k * 3 + c];
        out[G_CNT * 9 + (g * 20 + n) * 3 + c] = acc;
    }
}

// ---------------- launch ----------------
extern "C" void kernel_launch(void* const* d_in, const int* in_sizes, int n_in,
                              void* d_out, int out_size) {
    const int*   atom_types = (const int*)d_in[0];
    const float* frac       = (const float*)d_in[1];
    const float* lattices   = (const float*)d_in[2];
    const float* t          = (const float*)d_in[3];
    // d_in[4..6]: edge_index / edge2graph / node2graph — structure is derived analytically
    const float* emb_table  = (const float*)d_in[7];
    const float* w_latent   = (const float*)d_in[8];
    const float* b_latent   = (const float*)d_in[9];
    const float* ew1        = (const float*)d_in[10];
    const float* eb1        = (const float*)d_in[11];
    const float* ew2        = (const float*)d_in[12];
    const float* eb2        = (const float*)d_in[13];
    const float* nw1        = (const float*)d_in[14];
    const float* nb1        = (const float*)d_in[15];
    const float* nw2        = (const float*)d_in[16];
    const float* nb2        = (const float*)d_in[17];
    const float* coord_w    = (const float*)d_in[18];
    const float* lattice_w  = (const float*)d_in[19];
    float* out = (float*)d_out;

    const int EDGE_SMEM = 36960 * 4; // 147840 B
    cudaFuncSetAttribute(k_edge, cudaFuncAttributeMaxDynamicSharedMemorySize, EDGE_SMEM);

    k_latip<<<G_CNT, 32>>>(lattices);
    k_embed<<<G_CNT, 128>>>(atom_types, t, emb_table, w_latent, b_latent);
    k_dis<<<E_CNT / 256, 256>>>(frac);
    for (int i = 0; i < NLAYER; ++i) {
        k_nodeside<<<G_CNT, 128>>>(ew1 + i * 325 * 128, eb1 + i * 128);
        k_edge<<<G_CNT, 256, EDGE_SMEM>>>(ew1 + i * 325 * 128, ew2 + i * 128 * 128,
                                          eb2 + i * 128);
        k_nodemlp<<<G_CNT, 128>>>(nw1 + i * 256 * 128, nb1 + i * 128,
                                  nw2 + i * 128 * 128, nb2 + i * 128);
    }
    k_final<<<G_CNT, 128>>>(lattices, coord_w, lattice_w, out);
}

// round 3
// speedup vs baseline: 1.2583x; 1.2583x over previous
#include <cuda_runtime.h>
#include <cuda_bf16.h>
#include <math.h>

#define G_CNT 1024
#define A_CNT 20
#define N_CNT (G_CNT * A_CNT)          // 20480
#define E_CNT (G_CNT * A_CNT * A_CNT)  // 409600
#define H_DIM 128
#define NLAYER 4

// ---------------- scratch (device globals; no runtime allocation) ----------
__device__ float g_h[N_CNT * H_DIM];
__device__ float g_hs[N_CNT * H_DIM];
__device__ float g_hd[N_CNT * H_DIM];
__device__ float g_agg[N_CNT * H_DIM];
__device__ float g_latip[G_CNT * 9];
__device__ float g_latterm[G_CNT * H_DIM];
__device__ float g_disT[G_CNT * 60 * 400];  // per-graph transposed [g][k][r]

typedef unsigned long long u64;

__device__ __forceinline__ float siluf(float x) {
    return x / (1.0f + __expf(-x));
}
__device__ __forceinline__ u64 pack2(float x, float y) {
    u64 r;
    asm("mov.b64 %0, {%1, %2};" : "=l"(r) : "f"(x), "f"(y));
    return r;
}
__device__ __forceinline__ void unpack2(u64 v, float& x, float& y) {
    asm("mov.b64 {%0, %1}, %2;" : "=f"(x), "=f"(y) : "l"(v));
}
__device__ __forceinline__ void ffma2(u64& d, u64 a, u64 b) {
    asm("fma.rn.f32x2 %0, %1, %2, %0;" : "+l"(d) : "l"(a), "l"(b));
}
// acc (10 packed pairs = 20 floats) += a[0..19] * w  ; a 16B-aligned smem ptr
__device__ __forceinline__ void fma20p(u64 acc[10], const float* __restrict__ a, u64 w) {
#pragma unroll
    for (int q = 0; q < 5; ++q) {
        ulonglong2 v = reinterpret_cast<const ulonglong2*>(a)[q];
        ffma2(acc[2 * q], v.x, w);
        ffma2(acc[2 * q + 1], v.y, w);
    }
}

// ---------------- lat_ip = L @ L^T ----------------
__global__ void k_latip(const float* __restrict__ lattices) {
    int g = blockIdx.x, tid = threadIdx.x;
    if (tid < 9) {
        int i = tid / 3, k = tid % 3;
        float s = 0.f;
#pragma unroll
        for (int j = 0; j < 3; ++j)
            s += lattices[g * 9 + i * 3 + j] * lattices[g * 9 + k * 3 + j];
        g_latip[g * 9 + tid] = s;
    }
}

// ---------------- dis embedding via rotation recurrence ----------------
__global__ __launch_bounds__(256) void k_dis(const float* __restrict__ fc) {
    int e = blockIdx.x * 256 + threadIdx.x;
    if (e >= E_CNT) return;
    int g = e / 400;
    int r = e % 400;
    int src = g * 20 + r / 20;
    int dst = g * 20 + r % 20;
    float* base = g_disT + (size_t)g * 24000;
#pragma unroll
    for (int c = 0; c < 3; ++c) {
        float d = fc[dst * 3 + c] - fc[src * 3 + c];
        d -= floorf(d);
        float s1, c1;
        sincospif(2.0f * d, &s1, &c1);  // sin/cos(2*pi*d)
        float s = 0.f, co = 1.f;        // f = 0
        base[(c * 10) * 400 + r] = 0.f;
        base[(30 + c * 10) * 400 + r] = 1.f;
#pragma unroll
        for (int f = 1; f < 10; ++f) {
            float ns = s * c1 + co * s1;
            float nc = co * c1 - s * s1;
            s = ns; co = nc;
            base[(c * 10 + f) * 400 + r] = s;
            base[(30 + c * 10 + f) * 400 + r] = co;
        }
    }
}

// ---------------- node embedding + latent conditioning ----------------
__global__ __launch_bounds__(128) void k_embed(
    const int* __restrict__ atom_types, const float* __restrict__ t,
    const float* __restrict__ emb_table, const float* __restrict__ w_latent,
    const float* __restrict__ b_latent)
{
    __shared__ __align__(16) float inT[384 * 20];
    __shared__ int at[20];
    int g = blockIdx.x, tid = threadIdx.x;
    if (tid < 20) at[tid] = atom_types[g * 20 + tid];
    __syncthreads();
    for (int n = 0; n < 20; ++n)
        inT[tid * 20 + n] = emb_table[at[n] * H_DIM + tid];
    for (int k = tid; k < 256; k += 128) {
        float v = t[g * 256 + k];
#pragma unroll
        for (int n = 0; n < 20; ++n) inT[(128 + k) * 20 + n] = v;
    }
    __syncthreads();
    float b = b_latent[tid];
    u64 acc[10];
#pragma unroll
    for (int i = 0; i < 10; ++i) acc[i] = pack2(b, b);
#pragma unroll 4
    for (int k = 0; k < 384; ++k) {
        float w = w_latent[k * H_DIM + tid];
        fma20p(acc, &inT[k * 20], pack2(w, w));
    }
#pragma unroll
    for (int i = 0; i < 10; ++i) {
        float a0, a1;
        unpack2(acc[i], a0, a1);
        g_h[(g * 20 + 2 * i) * H_DIM + tid] = a0;
        g_h[(g * 20 + 2 * i + 1) * H_DIM + tid] = a1;
    }
}

// ---------------- per-layer node-side precompute: hs, hd, lat_term --------
__global__ __launch_bounds__(128) void k_nodeside(
    const float* __restrict__ ew1, const float* __restrict__ eb1)
{
    __shared__ __align__(16) float hT[128 * 20];
    int g = blockIdx.x, tid = threadIdx.x;
    for (int n = 0; n < 20; ++n)
        hT[tid * 20 + n] = g_h[(g * 20 + n) * H_DIM + tid];
    __syncthreads();
    u64 as[10], ad[10];
#pragma unroll
    for (int i = 0; i < 10; ++i) { as[i] = pack2(0.f, 0.f); ad[i] = pack2(0.f, 0.f); }
#pragma unroll 2
    for (int k = 0; k < 128; ++k) {
        float ws = ew1[k * H_DIM + tid];
        float wd = ew1[(128 + k) * H_DIM + tid];
        const float* a = &hT[k * 20];
        fma20p(as, a, pack2(ws, ws));
        fma20p(ad, a, pack2(wd, wd));
    }
#pragma unroll
    for (int i = 0; i < 10; ++i) {
        float a0, a1;
        unpack2(as[i], a0, a1);
        g_hs[(g * 20 + 2 * i) * H_DIM + tid] = a0;
        g_hs[(g * 20 + 2 * i + 1) * H_DIM + tid] = a1;
        unpack2(ad[i], a0, a1);
        g_hd[(g * 20 + 2 * i) * H_DIM + tid] = a0;
        g_hd[(g * 20 + 2 * i + 1) * H_DIM + tid] = a1;
    }
    float lt = eb1[tid];
#pragma unroll
    for (int j = 0; j < 9; ++j)
        lt += g_latip[g * 9 + j] * ew1[(256 + j) * H_DIM + tid];
    g_latterm[g * H_DIM + tid] = lt;
}

// ---------------- per-layer edge kernel (the big one) ----------------
// block = 1 graph (400 edges), 512 threads. pass p handles srcs {4p..4p+3};
// thread (ss=tid/128) owns one src's 20 edges for one output column.
// dis for pass p+1 is register-prefetched before phase B and stored after it.
__global__ __launch_bounds__(512) void k_edge(
    const float* __restrict__ ew1, const float* __restrict__ ew2,
    const float* __restrict__ eb2)
{
    extern __shared__ __align__(16) float sm[];
    float* smW1d = sm;                 // 7680
    float* smW2  = sm + 7680;          // 16384
    float* smB2  = sm + 24064;         // 128
    float* smHs  = sm + 24192;         // 2560
    float* smHd  = sm + 26752;         // 2560
    float* smLat = sm + 29312;         // 128
    float* smEf  = sm + 29440;         // 128*84 = 10752 (padded stride)
    float* smDis = sm + 40192;         // 60*80  = 4800
    int g = blockIdx.x, tid = threadIdx.x;

    {
        const float4* w1dv = (const float4*)(ew1 + 265 * H_DIM);
        for (int i = tid; i < 1920; i += 512) ((float4*)smW1d)[i] = w1dv[i];
        const float4* w2v = (const float4*)ew2;
        for (int i = tid; i < 4096; i += 512) ((float4*)smW2)[i] = w2v[i];
        const float4* hsv = (const float4*)(g_hs + g * 2560);
        const float4* hdv = (const float4*)(g_hd + g * 2560);
        for (int i = tid; i < 640; i += 512) {
            ((float4*)smHs)[i] = hsv[i];
            ((float4*)smHd)[i] = hdv[i];
        }
        if (tid < 128) {
            smB2[tid] = eb2[tid];
            smLat[tid] = g_latterm[g * H_DIM + tid];
        }
    }
    const float* disG = g_disT + (size_t)g * 24000;
    // stage pass 0: smDis[k*80 + l] = disG[k*400 + l]
    for (int i = tid; i < 4800; i += 512)
        smDis[i] = disG[(i / 80) * 400 + (i % 80)];
    __syncthreads();

    int col = tid & 127;
    int ss = tid >> 7;
    float b2v = smB2[col];
    float hlat = smLat[col];
    const float* disS = smDis + ss * 20;
    const float* efS = smEf + ss * 20;
    float* efW = smEf + col * 84 + ss * 20;

    for (int p = 0; p < 5; ++p) {
        int s = 4 * p + ss;
        // ---- phase A: separable preact + dis GEMM + silu ----
        u64 acc[10];
        float hsl = smHs[s * H_DIM + col] + hlat;
#pragma unroll
        for (int i = 0; i < 10; ++i)
            acc[i] = pack2(hsl + smHd[(2 * i) * H_DIM + col],
                           hsl + smHd[(2 * i + 1) * H_DIM + col]);
#pragma unroll 4
        for (int k = 0; k < 60; ++k) {
            float w = smW1d[k * H_DIM + col];
            fma20p(acc, disS + k * 80, pack2(w, w));
        }
#pragma unroll
        for (int i = 0; i < 5; ++i) {
            float a0, a1, a2, a3;
            unpack2(acc[2 * i], a0, a1);
            unpack2(acc[2 * i + 1], a2, a3);
            float4 v;
            v.x = siluf(a0); v.y = siluf(a1); v.z = siluf(a2); v.w = siluf(a3);
            ((float4*)efW)[i] = v;
        }
        __syncthreads();

        // ---- prefetch next pass's dis into registers (latency hidden by B) --
        float stg[10];
        if (p < 4) {
#pragma unroll
            for (int q = 0; q < 10; ++q) {
                int i = tid + q * 512;
                if (i < 4800)
                    stg[q] = disG[(i / 80) * 400 + (p + 1) * 80 + (i % 80)];
            }
        }

        // ---- phase B: ef @ W2 + silu + mean over 20 edges of src s ----
        u64 acc2[10];
#pragma unroll
        for (int i = 0; i < 10; ++i) acc2[i] = pack2(b2v, b2v);
#pragma unroll 4
        for (int k = 0; k < 128; ++k) {
            float w = smW2[k * H_DIM + col];
            fma20p(acc2, efS + k * 84, pack2(w, w));
        }
        float ssum = 0.f;
#pragma unroll
        for (int i = 0; i < 10; ++i) {
            float a0, a1;
            unpack2(acc2[i], a0, a1);
            ssum += siluf(a0) + siluf(a1);
        }
        g_agg[(g * 20 + s) * H_DIM + col] = ssum * 0.05f;

        if (p < 4) {
#pragma unroll
            for (int q = 0; q < 10; ++q) {
                int i = tid + q * 512;
                if (i < 4800) smDis[i] = stg[q];
            }
        }
        __syncthreads();
    }
}

// ---------------- per-layer node MLP + residual ----------------
__global__ __launch_bounds__(128) void k_nodemlp(
    const float* __restrict__ nw1, const float* __restrict__ nb1,
    const float* __restrict__ nw2, const float* __restrict__ nb2)
{
    __shared__ __align__(16) float inT[256 * 20];
    __shared__ __align__(16) float nfT[128 * 20];
    int g = blockIdx.x, tid = threadIdx.x;
    for (int n = 0; n < 20; ++n) {
        inT[tid * 20 + n] = g_h[(g * 20 + n) * H_DIM + tid];
        inT[(128 + tid) * 20 + n] = g_agg[(g * 20 + n) * H_DIM + tid];
    }
    __syncthreads();
    float b1 = nb1[tid];
    u64 acc[10];
#pragma unroll
    for (int i = 0; i < 10; ++i) acc[i] = pack2(b1, b1);
#pragma unroll 4
    for (int k = 0; k < 256; ++k) {
        float w = nw1[k * H_DIM + tid];
        fma20p(acc, &inT[k * 20], pack2(w, w));
    }
#pragma unroll
    for (int i = 0; i < 5; ++i) {
        float a0, a1, a2, a3;
        unpack2(acc[2 * i], a0, a1);
        unpack2(acc[2 * i + 1], a2, a3);
        float4 v;
        v.x = siluf(a0); v.y = siluf(a1); v.z = siluf(a2); v.w = siluf(a3);
        ((float4*)&nfT[tid * 20])[i] = v;
    }
    __syncthreads();
    float b2 = nb2[tid];
    u64 acc2[10];
#pragma unroll
    for (int i = 0; i < 10; ++i) acc2[i] = pack2(b2, b2);
#pragma unroll 4
    for (int k = 0; k < 128; ++k) {
        float w = nw2[k * H_DIM + tid];
        fma20p(acc2, &nfT[k * 20], pack2(w, w));
    }
#pragma unroll
    for (int i = 0; i < 10; ++i) {
        float a0, a1;
        unpack2(acc2[i], a0, a1);
        g_h[(g * 20 + 2 * i) * H_DIM + tid] = inT[tid * 20 + 2 * i] + siluf(a0);
        g_h[(g * 20 + 2 * i + 1) * H_DIM + tid] = inT[tid * 20 + 2 * i + 1] + siluf(a1);
    }
}

// ---------------- output heads ----------------
__global__ __launch_bounds__(128) void k_final(
    const float* __restrict__ lattices, const float* __restrict__ coord_w,
    const float* __restrict__ lattice_w, float* __restrict__ out)
{
    __shared__ __align__(16) float hT[128 * 20];
    __shared__ float gf[128];
    __shared__ float pre[9];
    int g = blockIdx.x, tid = threadIdx.x;
    for (int n = 0; n < 20; ++n)
        hT[tid * 20 + n] = g_h[(g * 20 + n) * H_DIM + tid];
    __syncthreads();
    float s = 0.f;
#pragma unroll
    for (int n = 0; n < 20; ++n) s += hT[tid * 20 + n];
    gf[tid] = s * 0.05f;
    __syncthreads();
    if (tid < 9) {
        float acc = 0.f;
        for (int k = 0; k < 128; ++k) acc += gf[k] * lattice_w[k * 9 + tid];
        pre[tid] = acc;
    }
    __syncthreads();
    if (tid < 9) {
        int i = tid / 3, kk = tid % 3;
        float v = 0.f;
#pragma unroll
        for (int j = 0; j < 3; ++j)
            v += pre[i * 3 + j] * lattices[g * 9 + j * 3 + kk];
        out[g * 9 + tid] = v;
    }
    if (tid < 60) {
        int n = tid / 3, c = tid % 3;
        float acc = 0.f;
        for (int k = 0; k < 128; ++k) acc += hT[k * 20 + n] * coord_w[k * 3 + c];
        out[G_CNT * 9 + (g * 20 + n) * 3 + c] = acc;
    }
}

// ---------------- launch ----------------
extern "C" void kernel_launch(void* const* d_in, const int* in_sizes, int n_in,
                              void* d_out, int out_size) {
    const int*   atom_types = (const int*)d_in[0];
    const float* frac       = (const float*)d_in[1];
    const float* lattices   = (const float*)d_in[2];
    const float* t          = (const float*)d_in[3];
    const float* emb_table  = (const float*)d_in[7];
    const float* w_latent   = (const float*)d_in[8];
    const float* b_latent   = (const float*)d_in[9];
    const float* ew1        = (const float*)d_in[10];
    const float* eb1        = (const float*)d_in[11];
    const float* ew2        = (const float*)d_in[12];
    const float* eb2        = (const float*)d_in[13];
    const float* nw1        = (const float*)d_in[14];
    const float* nb1        = (const float*)d_in[15];
    const float* nw2        = (const float*)d_in[16];
    const float* nb2        = (const float*)d_in[17];
    const float* coord_w    = (const float*)d_in[18];
    const float* lattice_w  = (const float*)d_in[19];
    float* out = (float*)d_out;

    const int EDGE_SMEM = 44992 * 4;  // 179968 B
    cudaFuncSetAttribute(k_edge, cudaFuncAttributeMaxDynamicSharedMemorySize, EDGE_SMEM);

    k_latip<<<G_CNT, 32>>>(lattices);
    k_embed<<<G_CNT, 128>>>(atom_types, t, emb_table, w_latent, b_latent);
    k_dis<<<E_CNT / 256, 256>>>(frac);
    for (int i = 0; i < NLAYER; ++i) {
        k_nodeside<<<G_CNT, 128>>>(ew1 + i * 325 * 128, eb1 + i * 128);
        k_edge<<<G_CNT, 512, EDGE_SMEM>>>(ew1 + i * 325 * 128, ew2 + i * 128 * 128,
                                          eb2 + i * 128);
        k_nodemlp<<<G_CNT, 128>>>(nw1 + i * 256 * 128, nb1 + i * 128,
                                  nw2 + i * 128 * 128, nb2 + i * 128);
    }
    k_final<<<G_CNT, 128>>>(lattices, coord_w, lattice_w, out);
}

// round 5
// speedup vs baseline: 1.7777x; 1.4127x over previous
#include <cuda_runtime.h>
#include <cuda_bf16.h>
#include <math.h>
#include <stdint.h>

#define G_CNT 1024
#define A_CNT 20
#define N_CNT (G_CNT * A_CNT)          // 20480
#define E_CNT (G_CNT * A_CNT * A_CNT)  // 409600
#define H_DIM 128
#define NLAYER 4

typedef unsigned long long u64;
typedef unsigned int u32;
typedef unsigned short u16;

// ---------------- scratch (device globals) ----------------
__device__ float g_h[N_CNT * H_DIM];
__device__ float g_hs[N_CNT * H_DIM];
__device__ float g_hd[N_CNT * H_DIM];
__device__ float g_agg[N_CNT * H_DIM];
__device__ float g_latip[G_CNT * 9];
__device__ float g_latterm[G_CNT * H_DIM];
// dis embedding as split bf16, [edge][64] (60 real + 4 zero pad), row-major
__device__ u16 g_disHi[(size_t)E_CNT * 64];
__device__ u16 g_disLo[(size_t)E_CNT * 64];

__device__ __forceinline__ float siluf(float x) { return x / (1.0f + __expf(-x)); }

__device__ __forceinline__ void split_bf(float x, u16& h, u16& l) {
    __nv_bfloat16 hb = __float2bfloat16_rn(x);
    float hf = __bfloat162float(hb);
    __nv_bfloat16 lb = __float2bfloat16_rn(x - hf);
    h = __bfloat16_as_ushort(hb);
    l = __bfloat16_as_ushort(lb);
}

__device__ __forceinline__ void mma16816(float c[4], const u32 a[4], u32 b0, u32 b1) {
    asm volatile(
        "mma.sync.aligned.m16n8k16.row.col.f32.bf16.bf16.f32 "
        "{%0,%1,%2,%3}, {%4,%5,%6,%7}, {%8,%9}, {%0,%1,%2,%3};"
        : "+f"(c[0]), "+f"(c[1]), "+f"(c[2]), "+f"(c[3])
        : "r"(a[0]), "r"(a[1]), "r"(a[2]), "r"(a[3]), "r"(b0), "r"(b1));
}

// fp32x2 packed helpers (scalar kernels)
__device__ __forceinline__ u64 pack2(float x, float y) {
    u64 r; asm("mov.b64 %0, {%1, %2};" : "=l"(r) : "f"(x), "f"(y)); return r;
}
__device__ __forceinline__ void unpack2(u64 v, float& x, float& y) {
    asm("mov.b64 {%0, %1}, %2;" : "=f"(x), "=f"(y) : "l"(v));
}
__device__ __forceinline__ void ffma2(u64& d, u64 a, u64 b) {
    asm("fma.rn.f32x2 %0, %1, %2, %0;" : "+l"(d) : "l"(a), "l"(b));
}
__device__ __forceinline__ void fma20p(u64 acc[10], const float* __restrict__ a, u64 w) {
#pragma unroll
    for (int q = 0; q < 5; ++q) {
        ulonglong2 v = reinterpret_cast<const ulonglong2*>(a)[q];
        ffma2(acc[2 * q], v.x, w);
        ffma2(acc[2 * q + 1], v.y, w);
    }
}

// ---------------- lat_ip = L @ L^T ----------------
__global__ void k_latip(const float* __restrict__ lattices) {
    int g = blockIdx.x, tid = threadIdx.x;
    if (tid < 9) {
        int i = tid / 3, k = tid % 3;
        float s = 0.f;
#pragma unroll
        for (int j = 0; j < 3; ++j)
            s += lattices[g * 9 + i * 3 + j] * lattices[g * 9 + k * 3 + j];
        g_latip[g * 9 + tid] = s;
    }
}

// ---------------- dis embedding -> split bf16, [e][64] ----------------
__global__ __launch_bounds__(128) void k_dis(const float* __restrict__ fc) {
    __shared__ u32 hiS[128 * 32];
    __shared__ u32 loS[128 * 32];
    int tid = threadIdx.x;
    size_t e0 = (size_t)blockIdx.x * 128;
    int e = (int)e0 + tid;
    int g = e / 400, r = e % 400;
    int src = g * 20 + r / 20;
    int dst = g * 20 + r % 20;
    u16* hrow = (u16*)hiS + tid * 64;
    u16* lrow = (u16*)loS + tid * 64;
#pragma unroll
    for (int c = 0; c < 3; ++c) {
        float d = fc[dst * 3 + c] - fc[src * 3 + c];
        d -= floorf(d);
        float s1, c1;
        sincospif(2.0f * d, &s1, &c1);
        float s = 0.f, co = 1.f;
        u16 h, l;
        split_bf(0.f, h, l); hrow[c * 10] = h; lrow[c * 10] = l;
        split_bf(1.f, h, l); hrow[30 + c * 10] = h; lrow[30 + c * 10] = l;
#pragma unroll
        for (int f = 1; f < 10; ++f) {
            float ns = s * c1 + co * s1;
            float nc = co * c1 - s * s1;
            s = ns; co = nc;
            split_bf(s, h, l); hrow[c * 10 + f] = h; lrow[c * 10 + f] = l;
            split_bf(co, h, l); hrow[30 + c * 10 + f] = h; lrow[30 + c * 10 + f] = l;
        }
    }
#pragma unroll
    for (int k = 60; k < 64; ++k) { hrow[k] = 0; lrow[k] = 0; }
    __syncthreads();
    u32* gh = (u32*)g_disHi + e0 * 32;
    u32* gl = (u32*)g_disLo + e0 * 32;
    for (int i = tid; i < 4096; i += 128) { gh[i] = hiS[i]; gl[i] = loS[i]; }
}

// ---------------- node embedding + latent conditioning ----------------
__global__ __launch_bounds__(128) void k_embed(
    const int* __restrict__ atom_types, const float* __restrict__ t,
    const float* __restrict__ emb_table, const float* __restrict__ w_latent,
    const float* __restrict__ b_latent)
{
    __shared__ __align__(16) float inT[384 * 20];
    __shared__ int at[20];
    int g = blockIdx.x, tid = threadIdx.x;
    if (tid < 20) at[tid] = atom_types[g * 20 + tid];
    __syncthreads();
    for (int n = 0; n < 20; ++n)
        inT[tid * 20 + n] = emb_table[at[n] * H_DIM + tid];
    for (int k = tid; k < 256; k += 128) {
        float v = t[g * 256 + k];
#pragma unroll
        for (int n = 0; n < 20; ++n) inT[(128 + k) * 20 + n] = v;
    }
    __syncthreads();
    float b = b_latent[tid];
    u64 acc[10];
#pragma unroll
    for (int i = 0; i < 10; ++i) acc[i] = pack2(b, b);
#pragma unroll 4
    for (int k = 0; k < 384; ++k) {
        float w = w_latent[k * H_DIM + tid];
        fma20p(acc, &inT[k * 20], pack2(w, w));
    }
#pragma unroll
    for (int i = 0; i < 10; ++i) {
        float a0, a1;
        unpack2(acc[i], a0, a1);
        g_h[(g * 20 + 2 * i) * H_DIM + tid] = a0;
        g_h[(g * 20 + 2 * i + 1) * H_DIM + tid] = a1;
    }
}

// ---------------- per-layer node-side precompute ----------------
__global__ __launch_bounds__(128) void k_nodeside(
    const float* __restrict__ ew1, const float* __restrict__ eb1)
{
    __shared__ __align__(16) float hT[128 * 20];
    int g = blockIdx.x, tid = threadIdx.x;
    for (int n = 0; n < 20; ++n)
        hT[tid * 20 + n] = g_h[(g * 20 + n) * H_DIM + tid];
    __syncthreads();
    u64 as[10], ad[10];
#pragma unroll
    for (int i = 0; i < 10; ++i) { as[i] = pack2(0.f, 0.f); ad[i] = pack2(0.f, 0.f); }
#pragma unroll 2
    for (int k = 0; k < 128; ++k) {
        float ws = ew1[k * H_DIM + tid];
        float wd = ew1[(128 + k) * H_DIM + tid];
        const float* a = &hT[k * 20];
        fma20p(as, a, pack2(ws, ws));
        fma20p(ad, a, pack2(wd, wd));
    }
#pragma unroll
    for (int i = 0; i < 10; ++i) {
        float a0, a1;
        unpack2(as[i], a0, a1);
        g_hs[(g * 20 + 2 * i) * H_DIM + tid] = a0;
        g_hs[(g * 20 + 2 * i + 1) * H_DIM + tid] = a1;
        unpack2(ad[i], a0, a1);
        g_hd[(g * 20 + 2 * i) * H_DIM + tid] = a0;
        g_hd[(g * 20 + 2 * i + 1) * H_DIM + tid] = a1;
    }
    float lt = eb1[tid];
#pragma unroll
    for (int j = 0; j < 9; ++j)
        lt += g_latip[g * 9 + j] * ew1[(256 + j) * H_DIM + tid];
    g_latterm[g * H_DIM + tid] = lt;
}

// ---------------- tensor (mma.sync) edge kernel ----------------
// block = 1 graph, 256 threads = 8 warps; 400 edges = 25 tiles x 16 rows.
// Each warp owns whole tiles (tt = w, w+8, ...): GEMM1 -> epilogue A ->
// GEMM2 -> epilogue B -> per-tile column partials. No intra-loop block sync.
// smem byte offsets:
#define SW1H 0          // W1d hi [n=128][k stride 72] 18432
#define SW1L 18432
#define SW2H 36864      // W2 hi [n=128][k stride 136] 34816
#define SW2L 71680
#define SAW  106496     // 8 warps x 8704 (A tile hi/lo | ef buffer)
#define SHS  176128     // hs 20x128 f32
#define SHD  186368
#define SLAT 196608
#define SB2  197120
#define SPART 197632    // partial [25][2][128] f32 = 25600
#define SM_TOT 223232

__global__ __launch_bounds__(256, 1) void k_edge_m(
    const float* __restrict__ ew1, const float* __restrict__ ew2,
    const float* __restrict__ eb2)
{
    extern __shared__ char sm[];
    int tid = threadIdx.x, g0 = blockIdx.x;
    int w = tid >> 5, lane = tid & 31;
    int gq = lane >> 2, tig = lane & 3;

    // ---- stage weights (split bf16) ----
    for (int idx = tid; idx < 8192; idx += 256) {
        int n = idx & 127, k = idx >> 7;
        float v = (k < 60) ? ew1[(265 + k) * H_DIM + n] : 0.f;
        u16 h, l; split_bf(v, h, l);
        *(u16*)(sm + SW1H + (n * 72 + k) * 2) = h;
        *(u16*)(sm + SW1L + (n * 72 + k) * 2) = l;
    }
    for (int idx = tid; idx < 16384; idx += 256) {
        int n = idx & 127, k = idx >> 7;
        float v = ew2[k * H_DIM + n];
        u16 h, l; split_bf(v, h, l);
        *(u16*)(sm + SW2H + (n * 136 + k) * 2) = h;
        *(u16*)(sm + SW2L + (n * 136 + k) * 2) = l;
    }
    float* hs = (float*)(sm + SHS);
    float* hd = (float*)(sm + SHD);
    for (int i = tid; i < 2560; i += 256) {
        hs[i] = g_hs[g0 * 2560 + i];
        hd[i] = g_hd[g0 * 2560 + i];
    }
    if (tid < 128) {
        ((float*)(sm + SLAT))[tid] = g_latterm[g0 * H_DIM + tid];
        ((float*)(sm + SB2))[tid] = eb2[tid];
    }
    __syncthreads();

    char* AB = sm + SAW + w * 8704;   // per-warp A hi (dis stride 144B / A2 stride 272B)
    char* ABl = AB + 4352;            // A lo
    float* lat = (float*)(sm + SLAT);
    float* b2 = (float*)(sm + SB2);
    float* part = (float*)(sm + SPART);

    for (int tt = w; tt < 25; tt += 8) {
        int e0 = tt * 16;
        // ---- stage dis tile [16][64] hi/lo, row stride 72 halves ----
        {
            const uint4* sH = (const uint4*)(g_disHi + ((size_t)g0 * 400 + e0) * 64);
            const uint4* sL = (const uint4*)(g_disLo + ((size_t)g0 * 400 + e0) * 64);
#pragma unroll
            for (int q = 0; q < 4; ++q) {
                int idx = lane + q * 32;
                int row = idx >> 3, seg = idx & 7;
                *(uint4*)(AB + row * 144 + seg * 16) = sH[row * 8 + seg];
                *(uint4*)(ABl + row * 144 + seg * 16) = sL[row * 8 + seg];
            }
        }
        __syncwarp();

        // ---- GEMM1: acc[16 ntiles][4] = dis[16,64] @ W1d[64,128] (3 split mma) ----
        float acc[16][4];
#pragma unroll
        for (int j = 0; j < 16; ++j)
            acc[j][0] = acc[j][1] = acc[j][2] = acc[j][3] = 0.f;
#pragma unroll
        for (int ks = 0; ks < 4; ++ks) {
            int kc = ks * 16 + 2 * tig;
            u32 ah[4], al[4];
            ah[0] = *(const u32*)(AB + gq * 144 + kc * 2);
            ah[1] = *(const u32*)(AB + (gq + 8) * 144 + kc * 2);
            ah[2] = *(const u32*)(AB + gq * 144 + (kc + 8) * 2);
            ah[3] = *(const u32*)(AB + (gq + 8) * 144 + (kc + 8) * 2);
            al[0] = *(const u32*)(ABl + gq * 144 + kc * 2);
            al[1] = *(const u32*)(ABl + (gq + 8) * 144 + kc * 2);
            al[2] = *(const u32*)(ABl + gq * 144 + (kc + 8) * 2);
            al[3] = *(const u32*)(ABl + (gq + 8) * 144 + (kc + 8) * 2);
#pragma unroll
            for (int j = 0; j < 16; ++j) {
                const char* bh = sm + SW1H + ((j * 8 + gq) * 72 + kc) * 2;
                const char* bl = sm + SW1L + ((j * 8 + gq) * 72 + kc) * 2;
                u32 b0h = *(const u32*)bh, b1h = *(const u32*)(bh + 16);
                u32 b0l = *(const u32*)bl, b1l = *(const u32*)(bl + 16);
                mma16816(acc[j], ah, b0h, b1h);
                mma16816(acc[j], ah, b0l, b1l);
                mma16816(acc[j], al, b0h, b1h);
            }
        }
        __syncwarp();

        // ---- epilogue A: + hs[src] + hd[dst] + lat, silu, split -> A2 ----
        {
            int eA = e0 + gq, eB = e0 + gq + 8;
            int srcA = eA / 20, dstA = eA - srcA * 20;
            int srcB = eB / 20, dstB = eB - srcB * 20;
#pragma unroll
            for (int j = 0; j < 16; ++j) {
                int c0 = j * 8 + 2 * tig;
                float2 la = *(const float2*)&lat[c0];
                float2 hsA = *(const float2*)&hs[srcA * 128 + c0];
                float2 hdA = *(const float2*)&hd[dstA * 128 + c0];
                float2 hsB = *(const float2*)&hs[srcB * 128 + c0];
                float2 hdB = *(const float2*)&hd[dstB * 128 + c0];
                float x0 = siluf(acc[j][0] + hsA.x + hdA.x + la.x);
                float x1 = siluf(acc[j][1] + hsA.y + hdA.y + la.y);
                float x2 = siluf(acc[j][2] + hsB.x + hdB.x + la.x);
                float x3 = siluf(acc[j][3] + hsB.y + hdB.y + la.y);
                u16 h0, l0, h1, l1;
                split_bf(x0, h0, l0); split_bf(x1, h1, l1);
                *(u32*)(AB + gq * 272 + c0 * 2) = (u32)h0 | ((u32)h1 << 16);
                *(u32*)(ABl + gq * 272 + c0 * 2) = (u32)l0 | ((u32)l1 << 16);
                split_bf(x2, h0, l0); split_bf(x3, h1, l1);
                *(u32*)(AB + (gq + 8) * 272 + c0 * 2) = (u32)h0 | ((u32)h1 << 16);
                *(u32*)(ABl + (gq + 8) * 272 + c0 * 2) = (u32)l0 | ((u32)l1 << 16);
            }
        }
        __syncwarp();

        // ---- GEMM2: acc2 = ef[16,128] @ W2[128,128] (3 split mma) ----
        float acc2[16][4];
#pragma unroll
        for (int j = 0; j < 16; ++j)
            acc2[j][0] = acc2[j][1] = acc2[j][2] = acc2[j][3] = 0.f;
#pragma unroll
        for (int ks = 0; ks < 8; ++ks) {
            int kc = ks * 16 + 2 * tig;
            u32 ah[4], al[4];
            ah[0] = *(const u32*)(AB + gq * 272 + kc * 2);
            ah[1] = *(const u32*)(AB + (gq + 8) * 272 + kc * 2);
            ah[2] = *(const u32*)(AB + gq * 272 + (kc + 8) * 2);
            ah[3] = *(const u32*)(AB + (gq + 8) * 272 + (kc + 8) * 2);
            al[0] = *(const u32*)(ABl + gq * 272 + kc * 2);
            al[1] = *(const u32*)(ABl + (gq + 8) * 272 + kc * 2);
            al[2] = *(const u32*)(ABl + gq * 272 + (kc + 8) * 2);
            al[3] = *(const u32*)(ABl + (gq + 8) * 272 + (kc + 8) * 2);
#pragma unroll
            for (int j = 0; j < 16; ++j) {
                const char* bh = sm + SW2H + ((j * 8 + gq) * 136 + kc) * 2;
                const char* bl = sm + SW2L + ((j * 8 + gq) * 136 + kc) * 2;
                u32 b0h = *(const u32*)bh, b1h = *(const u32*)(bh + 16);
                u32 b0l = *(const u32*)bl, b1l = *(const u32*)(bl + 16);
                mma16816(acc2[j], ah, b0h, b1h);
                mma16816(acc2[j], ah, b0l, b1l);
                mma16816(acc2[j], al, b0h, b1h);
            }
        }
        __syncwarp();

        // ---- epilogue B: silu -> ef (f32, stride 132), column partials ----
        {
            float* ef = (float*)AB;
#pragma unroll
            for (int j = 0; j < 16; ++j) {
                int c0 = j * 8 + 2 * tig;
                float2 bb = *(const float2*)&b2[c0];
                float2 v0, v1;
                v0.x = siluf(acc2[j][0] + bb.x);
                v0.y = siluf(acc2[j][1] + bb.y);
                v1.x = siluf(acc2[j][2] + bb.x);
                v1.y = siluf(acc2[j][3] + bb.y);
                *(float2*)&ef[gq * 132 + c0] = v0;
                *(float2*)&ef[(gq + 8) * 132 + c0] = v1;
            }
            __syncwarp();
            int sA = e0 / 20;
            int bnd = 20 * (sA + 1) - e0;
            if (bnd > 16) bnd = 16;
#pragma unroll
            for (int cc = 0; cc < 4; ++cc) {
                int c = lane + cc * 32;
                float p0 = 0.f, p1 = 0.f;
#pragma unroll
                for (int r = 0; r < 16; ++r) {
                    float v = ef[r * 132 + c];
                    if (r < bnd) p0 += v; else p1 += v;
                }
                part[(tt * 2) * 128 + c] = p0;
                part[(tt * 2 + 1) * 128 + c] = p1;
            }
        }
        __syncwarp();
    }
    __syncthreads();

    // ---- combine partials -> scatter-mean ----
    for (int idx = tid; idx < 2560; idx += 256) {
        int s = idx >> 7, c = idx & 127;
        int t0 = (20 * s) >> 4, t1 = (20 * s + 19) >> 4;
        float a = 0.f;
        for (int t = t0; t <= t1; ++t) {
            int sA = (16 * t) / 20;
            int sB = (16 * t + 15) / 20;
            if (sA == s) a += part[t * 256 + c];
            else if (sB == s) a += part[t * 256 + 128 + c];
        }
        g_agg[g0 * 2560 + idx] = a * 0.05f;
    }
}

// ---------------- per-layer node MLP + residual ----------------
__global__ __launch_bounds__(128) void k_nodemlp(
    const float* __restrict__ nw1, const float* __restrict__ nb1,
    const float* __restrict__ nw2, const float* __restrict__ nb2)
{
    __shared__ __align__(16) float inT[256 * 20];
    __shared__ __align__(16) float nfT[128 * 20];
    int g = blockIdx.x, tid = threadIdx.x;
    for (int n = 0; n < 20; ++n) {
        inT[tid * 20 + n] = g_h[(g * 20 + n) * H_DIM + tid];
        inT[(128 + tid) * 20 + n] = g_agg[(g * 20 + n) * H_DIM + tid];
    }
    __syncthreads();
    float b1 = nb1[tid];
    u64 acc[10];
#pragma unroll
    for (int i = 0; i < 10; ++i) acc[i] = pack2(b1, b1);
#pragma unroll 4
    for (int k = 0; k < 256; ++k) {
        float w = nw1[k * H_DIM + tid];
        fma20p(acc, &inT[k * 20], pack2(w, w));
    }
#pragma unroll
    for (int i = 0; i < 5; ++i) {
        float a0, a1, a2, a3;
        unpack2(acc[2 * i], a0, a1);
        unpack2(acc[2 * i + 1], a2, a3);
        float4 v;
        v.x = siluf(a0); v.y = siluf(a1); v.z = siluf(a2); v.w = siluf(a3);
        ((float4*)&nfT[tid * 20])[i] = v;
    }
    __syncthreads();
    float b2 = nb2[tid];
    u64 acc2[10];
#pragma unroll
    for (int i = 0; i < 10; ++i) acc2[i] = pack2(b2, b2);
#pragma unroll 4
    for (int k = 0; k < 128; ++k) {
        float w = nw2[k * H_DIM + tid];
        fma20p(acc2, &nfT[k * 20], pack2(w, w));
    }
#pragma unroll
    for (int i = 0; i < 10; ++i) {
        float a0, a1;
        unpack2(acc2[i], a0, a1);
        g_h[(g * 20 + 2 * i) * H_DIM + tid] = inT[tid * 20 + 2 * i] + siluf(a0);
        g_h[(g * 20 + 2 * i + 1) * H_DIM + tid] = inT[tid * 20 + 2 * i + 1] + siluf(a1);
    }
}

// ---------------- output heads ----------------
__global__ __launch_bounds__(128) void k_final(
    const float* __restrict__ lattices, const float* __restrict__ coord_w,
    const float* __restrict__ lattice_w, float* __restrict__ out)
{
    __shared__ __align__(16) float hT[128 * 20];
    __shared__ float gf[128];
    __shared__ float pre[9];
    int g = blockIdx.x, tid = threadIdx.x;
    for (int n = 0; n < 20; ++n)
        hT[tid * 20 + n] = g_h[(g * 20 + n) * H_DIM + tid];
    __syncthreads();
    float s = 0.f;
#pragma unroll
    for (int n = 0; n < 20; ++n) s += hT[tid * 20 + n];
    gf[tid] = s * 0.05f;
    __syncthreads();
    if (tid < 9) {
        float acc = 0.f;
        for (int k = 0; k < 128; ++k) acc += gf[k] * lattice_w[k * 9 + tid];
        pre[tid] = acc;
    }
    __syncthreads();
    if (tid < 9) {
        int i = tid / 3, kk = tid % 3;
        float v = 0.f;
#pragma unroll
        for (int j = 0; j < 3; ++j)
            v += pre[i * 3 + j] * lattices[g * 9 + j * 3 + kk];
        out[g * 9 + tid] = v;
    }
    if (tid < 60) {
        int n = tid / 3, c = tid % 3;
        float acc = 0.f;
        for (int k = 0; k < 128; ++k) acc += hT[k * 20 + n] * coord_w[k * 3 + c];
        out[G_CNT * 9 + (g * 20 + n) * 3 + c] = acc;
    }
}

// ---------------- launch ----------------
extern "C" void kernel_launch(void* const* d_in, const int* in_sizes, int n_in,
                              void* d_out, int out_size) {
    const int*   atom_types = (const int*)d_in[0];
    const float* frac       = (const float*)d_in[1];
    const float* lattices   = (const float*)d_in[2];
    const float* t          = (const float*)d_in[3];
    const float* emb_table  = (const float*)d_in[7];
    const float* w_latent   = (const float*)d_in[8];
    const float* b_latent   = (const float*)d_in[9];
    const float* ew1        = (const float*)d_in[10];
    const float* eb1        = (const float*)d_in[11];
    const float* ew2        = (const float*)d_in[12];
    const float* eb2        = (const float*)d_in[13];
    const float* nw1        = (const float*)d_in[14];
    const float* nb1        = (const float*)d_in[15];
    const float* nw2        = (const float*)d_in[16];
    const float* nb2        = (const float*)d_in[17];
    const float* coord_w    = (const float*)d_in[18];
    const float* lattice_w  = (const float*)d_in[19];
    float* out = (float*)d_out;

    cudaFuncSetAttribute(k_edge_m, cudaFuncAttributeMaxDynamicSharedMemorySize, SM_TOT);

    k_latip<<<G_CNT, 32>>>(lattices);
    k_embed<<<G_CNT, 128>>>(atom_types, t, emb_table, w_latent, b_latent);
    k_dis<<<E_CNT / 128, 128>>>(frac);
    for (int i = 0; i < NLAYER; ++i) {
        k_nodeside<<<G_CNT, 128>>>(ew1 + i * 325 * 128, eb1 + i * 128);
        k_edge_m<<<G_CNT, 256, SM_TOT>>>(ew1 + i * 325 * 128,
                                         ew2 + i * 128 * 128, eb2 + i * 128);
        k_nodemlp<<<G_CNT, 128>>>(nw1 + i * 256 * 128, nb1 + i * 128,
                                  nw2 + i * 128 * 128, nb2 + i * 128);
    }
    k_final<<<G_CNT, 128>>>(lattices, coord_w, lattice_w, out);
}

// round 6
// speedup vs baseline: 2.6382x; 1.4841x over previous
#include <cuda_runtime.h>
#include <cuda_bf16.h>
#include <math.h>
#include <stdint.h>

#define G_CNT 1024
#define A_CNT 20
#define N_CNT (G_CNT * A_CNT)          // 20480
#define E_CNT (G_CNT * A_CNT * A_CNT)  // 409600
#define H_DIM 128
#define NLAYER 4

typedef unsigned long long u64;
typedef unsigned int u32;
typedef unsigned short u16;

// ---------------- scratch (device globals) ----------------
__device__ float g_h[N_CNT * H_DIM];
__device__ float g_hs[N_CNT * H_DIM];
__device__ float g_hd[N_CNT * H_DIM];
__device__ float g_agg[N_CNT * H_DIM];
__device__ float g_latip[G_CNT * 9];
__device__ float g_latterm[G_CNT * H_DIM];
// dis embedding as bf16, [edge][64] (60 real + 4 zero pad), row-major
__device__ u16 g_disHi[(size_t)E_CNT * 64];

__device__ __forceinline__ float siluf(float x) { return x / (1.0f + __expf(-x)); }

__device__ __forceinline__ void split_bf(float x, u16& h, u16& l) {
    __nv_bfloat16 hb = __float2bfloat16_rn(x);
    float hf = __bfloat162float(hb);
    __nv_bfloat16 lb = __float2bfloat16_rn(x - hf);
    h = __bfloat16_as_ushort(hb);
    l = __bfloat16_as_ushort(lb);
}
__device__ __forceinline__ u16 bf_rn(float x) {
    return __bfloat16_as_ushort(__float2bfloat16_rn(x));
}

__device__ __forceinline__ void mma16816(float c[4], const u32 a[4], u32 b0, u32 b1) {
    asm volatile(
        "mma.sync.aligned.m16n8k16.row.col.f32.bf16.bf16.f32 "
        "{%0,%1,%2,%3}, {%4,%5,%6,%7}, {%8,%9}, {%0,%1,%2,%3};"
        : "+f"(c[0]), "+f"(c[1]), "+f"(c[2]), "+f"(c[3])
        : "r"(a[0]), "r"(a[1]), "r"(a[2]), "r"(a[3]), "r"(b0), "r"(b1));
}

// fp32x2 packed helpers (scalar kernels)
__device__ __forceinline__ u64 pack2(float x, float y) {
    u64 r; asm("mov.b64 %0, {%1, %2};" : "=l"(r) : "f"(x), "f"(y)); return r;
}
__device__ __forceinline__ void unpack2(u64 v, float& x, float& y) {
    asm("mov.b64 {%0, %1}, %2;" : "=f"(x), "=f"(y) : "l"(v));
}
__device__ __forceinline__ void ffma2(u64& d, u64 a, u64 b) {
    asm("fma.rn.f32x2 %0, %1, %2, %0;" : "+l"(d) : "l"(a), "l"(b));
}
__device__ __forceinline__ void fma20p(u64 acc[10], const float* __restrict__ a, u64 w) {
#pragma unroll
    for (int q = 0; q < 5; ++q) {
        ulonglong2 v = reinterpret_cast<const ulonglong2*>(a)[q];
        ffma2(acc[2 * q], v.x, w);
        ffma2(acc[2 * q + 1], v.y, w);
    }
}

// ---------------- lat_ip = L @ L^T ----------------
__global__ void k_latip(const float* __restrict__ lattices) {
    int g = blockIdx.x, tid = threadIdx.x;
    if (tid < 9) {
        int i = tid / 3, k = tid % 3;
        float s = 0.f;
#pragma unroll
        for (int j = 0; j < 3; ++j)
            s += lattices[g * 9 + i * 3 + j] * lattices[g * 9 + k * 3 + j];
        g_latip[g * 9 + tid] = s;
    }
}

// ---------------- dis embedding -> bf16, [e][64] ----------------
__global__ __launch_bounds__(128) void k_dis(const float* __restrict__ fc) {
    __shared__ u32 hiS[128 * 32];
    int tid = threadIdx.x;
    size_t e0 = (size_t)blockIdx.x * 128;
    int e = (int)e0 + tid;
    int g = e / 400, r = e % 400;
    int src = g * 20 + r / 20;
    int dst = g * 20 + r % 20;
    u16* hrow = (u16*)hiS + tid * 64;
#pragma unroll
    for (int c = 0; c < 3; ++c) {
        float d = fc[dst * 3 + c] - fc[src * 3 + c];
        d -= floorf(d);
        float s1, c1;
        sincospif(2.0f * d, &s1, &c1);
        float s = 0.f, co = 1.f;
        hrow[c * 10] = bf_rn(0.f);
        hrow[30 + c * 10] = bf_rn(1.f);
#pragma unroll
        for (int f = 1; f < 10; ++f) {
            float ns = s * c1 + co * s1;
            float nc = co * c1 - s * s1;
            s = ns; co = nc;
            hrow[c * 10 + f] = bf_rn(s);
            hrow[30 + c * 10 + f] = bf_rn(co);
        }
    }
#pragma unroll
    for (int k = 60; k < 64; ++k) hrow[k] = 0;
    __syncthreads();
    u32* gh = (u32*)g_disHi + e0 * 32;
    for (int i = tid; i < 4096; i += 128) gh[i] = hiS[i];
}

// ---------------- node embedding + latent conditioning ----------------
__global__ __launch_bounds__(128) void k_embed(
    const int* __restrict__ atom_types, const float* __restrict__ t,
    const float* __restrict__ emb_table, const float* __restrict__ w_latent,
    const float* __restrict__ b_latent)
{
    __shared__ __align__(16) float inT[384 * 20];
    __shared__ int at[20];
    int g = blockIdx.x, tid = threadIdx.x;
    if (tid < 20) at[tid] = atom_types[g * 20 + tid];
    __syncthreads();
    for (int n = 0; n < 20; ++n)
        inT[tid * 20 + n] = emb_table[at[n] * H_DIM + tid];
    for (int k = tid; k < 256; k += 128) {
        float v = t[g * 256 + k];
#pragma unroll
        for (int n = 0; n < 20; ++n) inT[(128 + k) * 20 + n] = v;
    }
    __syncthreads();
    float b = b_latent[tid];
    u64 acc[10];
#pragma unroll
    for (int i = 0; i < 10; ++i) acc[i] = pack2(b, b);
#pragma unroll 4
    for (int k = 0; k < 384; ++k) {
        float w = w_latent[k * H_DIM + tid];
        fma20p(acc, &inT[k * 20], pack2(w, w));
    }
#pragma unroll
    for (int i = 0; i < 10; ++i) {
        float a0, a1;
        unpack2(acc[i], a0, a1);
        g_h[(g * 20 + 2 * i) * H_DIM + tid] = a0;
        g_h[(g * 20 + 2 * i + 1) * H_DIM + tid] = a1;
    }
}

// ---------------- per-layer node-side precompute ----------------
__global__ __launch_bounds__(128) void k_nodeside(
    const float* __restrict__ ew1, const float* __restrict__ eb1)
{
    __shared__ __align__(16) float hT[128 * 20];
    int g = blockIdx.x, tid = threadIdx.x;
    for (int n = 0; n < 20; ++n)
        hT[tid * 20 + n] = g_h[(g * 20 + n) * H_DIM + tid];
    __syncthreads();
    u64 as[10], ad[10];
#pragma unroll
    for (int i = 0; i < 10; ++i) { as[i] = pack2(0.f, 0.f); ad[i] = pack2(0.f, 0.f); }
#pragma unroll 2
    for (int k = 0; k < 128; ++k) {
        float ws = ew1[k * H_DIM + tid];
        float wd = ew1[(128 + k) * H_DIM + tid];
        const float* a = &hT[k * 20];
        fma20p(as, a, pack2(ws, ws));
        fma20p(ad, a, pack2(wd, wd));
    }
#pragma unroll
    for (int i = 0; i < 10; ++i) {
        float a0, a1;
        unpack2(as[i], a0, a1);
        g_hs[(g * 20 + 2 * i) * H_DIM + tid] = a0;
        g_hs[(g * 20 + 2 * i + 1) * H_DIM + tid] = a1;
        unpack2(ad[i], a0, a1);
        g_hd[(g * 20 + 2 * i) * H_DIM + tid] = a0;
        g_hd[(g * 20 + 2 * i + 1) * H_DIM + tid] = a1;
    }
    float lt = eb1[tid];
#pragma unroll
    for (int j = 0; j < 9; ++j)
        lt += g_latip[g * 9 + j] * ew1[(256 + j) * H_DIM + tid];
    g_latterm[g * H_DIM + tid] = lt;
}

// ---------------- tensor (mma.sync) edge kernel ----------------
// block = 1 graph, 512 threads = 16 warps; 400 edges = 25 tiles x 16 rows.
// A-side unsplit bf16; B-side (weights) split hi/lo -> 2 MMAs per site.
#define SW1H 0          // W1d hi [n=128][k stride 72] 18432
#define SW1L 18432
#define SW2H 36864      // W2 hi [n=128][k stride 136] 34816
#define SW2L 71680
#define SAW  106496     // 16 warps x 4352 (A tile | A2 | ef chunks)
#define SHS  176128     // hs 20x128 f32
#define SHD  186368
#define SLAT 196608
#define SB2  197120
#define SPART 197632    // partial [25][2][128] f32 = 25600
#define SM_TOT 223232

__global__ __launch_bounds__(512, 1) void k_edge_m(
    const float* __restrict__ ew1, const float* __restrict__ ew2,
    const float* __restrict__ eb2)
{
    extern __shared__ char sm[];
    int tid = threadIdx.x, g0 = blockIdx.x;
    int w = tid >> 5, lane = tid & 31;
    int gq = lane >> 2, tig = lane & 3;

    // ---- stage weights (split bf16) ----
    for (int idx = tid; idx < 8192; idx += 512) {
        int n = idx & 127, k = idx >> 7;
        float v = (k < 60) ? ew1[(265 + k) * H_DIM + n] : 0.f;
        u16 h, l; split_bf(v, h, l);
        *(u16*)(sm + SW1H + (n * 72 + k) * 2) = h;
        *(u16*)(sm + SW1L + (n * 72 + k) * 2) = l;
    }
    for (int idx = tid; idx < 16384; idx += 512) {
        int n = idx & 127, k = idx >> 7;
        float v = ew2[k * H_DIM + n];
        u16 h, l; split_bf(v, h, l);
        *(u16*)(sm + SW2H + (n * 136 + k) * 2) = h;
        *(u16*)(sm + SW2L + (n * 136 + k) * 2) = l;
    }
    float* hs = (float*)(sm + SHS);
    float* hd = (float*)(sm + SHD);
    for (int i = tid; i < 2560; i += 512) {
        hs[i] = g_hs[g0 * 2560 + i];
        hd[i] = g_hd[g0 * 2560 + i];
    }
    if (tid < 128) {
        ((float*)(sm + SLAT))[tid] = g_latterm[g0 * H_DIM + tid];
        ((float*)(sm + SB2))[tid] = eb2[tid];
    }
    __syncthreads();

    char* AB = sm + SAW + w * 4352;   // per-warp: dis (stride 144B) / A2 (stride 272B) / ef
    float* lat = (float*)(sm + SLAT);
    float* b2 = (float*)(sm + SB2);
    float* part = (float*)(sm + SPART);

    for (int tt = w; tt < 25; tt += 16) {
        int e0 = tt * 16;
        // ---- stage dis tile [16][64] bf16, row stride 72 halves ----
        {
            const uint4* sH = (const uint4*)(g_disHi + ((size_t)g0 * 400 + e0) * 64);
#pragma unroll
            for (int q = 0; q < 4; ++q) {
                int idx = lane + q * 32;
                int row = idx >> 3, seg = idx & 7;
                *(uint4*)(AB + row * 144 + seg * 16) = sH[row * 8 + seg];
            }
        }
        __syncwarp();

        // ---- GEMM1: dis[16,64] @ W1d[64,128], 2 MMAs per site ----
        float acc[16][4];
#pragma unroll
        for (int j = 0; j < 16; ++j)
            acc[j][0] = acc[j][1] = acc[j][2] = acc[j][3] = 0.f;
#pragma unroll
        for (int ks = 0; ks < 4; ++ks) {
            int kc = ks * 16 + 2 * tig;
            u32 ah[4];
            ah[0] = *(const u32*)(AB + gq * 144 + kc * 2);
            ah[1] = *(const u32*)(AB + (gq + 8) * 144 + kc * 2);
            ah[2] = *(const u32*)(AB + gq * 144 + (kc + 8) * 2);
            ah[3] = *(const u32*)(AB + (gq + 8) * 144 + (kc + 8) * 2);
#pragma unroll
            for (int j = 0; j < 16; ++j) {
                const char* bh = sm + SW1H + ((j * 8 + gq) * 72 + kc) * 2;
                const char* bl = sm + SW1L + ((j * 8 + gq) * 72 + kc) * 2;
                u32 b0h = *(const u32*)bh, b1h = *(const u32*)(bh + 16);
                u32 b0l = *(const u32*)bl, b1l = *(const u32*)(bl + 16);
                mma16816(acc[j], ah, b0h, b1h);
                mma16816(acc[j], ah, b0l, b1l);
            }
        }
        __syncwarp();

        // ---- epilogue A: + hs[src] + hd[dst] + lat, silu, bf16 -> A2 ----
        {
            int eA = e0 + gq, eB = e0 + gq + 8;
            int srcA = eA / 20, dstA = eA - srcA * 20;
            int srcB = eB / 20, dstB = eB - srcB * 20;
#pragma unroll
            for (int j = 0; j < 16; ++j) {
                int c0 = j * 8 + 2 * tig;
                float2 la = *(const float2*)&lat[c0];
                float2 hsA = *(const float2*)&hs[srcA * 128 + c0];
                float2 hdA = *(const float2*)&hd[dstA * 128 + c0];
                float2 hsB = *(const float2*)&hs[srcB * 128 + c0];
                float2 hdB = *(const float2*)&hd[dstB * 128 + c0];
                float x0 = siluf(acc[j][0] + hsA.x + hdA.x + la.x);
                float x1 = siluf(acc[j][1] + hsA.y + hdA.y + la.y);
                float x2 = siluf(acc[j][2] + hsB.x + hdB.x + la.x);
                float x3 = siluf(acc[j][3] + hsB.y + hdB.y + la.y);
                *(u32*)(AB + gq * 272 + c0 * 2) = (u32)bf_rn(x0) | ((u32)bf_rn(x1) << 16);
                *(u32*)(AB + (gq + 8) * 272 + c0 * 2) = (u32)bf_rn(x2) | ((u32)bf_rn(x3) << 16);
            }
        }
        __syncwarp();

        // ---- GEMM2: ef[16,128] @ W2[128,128], 2 MMAs per site ----
        float acc2[16][4];
#pragma unroll
        for (int j = 0; j < 16; ++j)
            acc2[j][0] = acc2[j][1] = acc2[j][2] = acc2[j][3] = 0.f;
#pragma unroll
        for (int ks = 0; ks < 8; ++ks) {
            int kc = ks * 16 + 2 * tig;
            u32 ah[4];
            ah[0] = *(const u32*)(AB + gq * 272 + kc * 2);
            ah[1] = *(const u32*)(AB + (gq + 8) * 272 + kc * 2);
            ah[2] = *(const u32*)(AB + gq * 272 + (kc + 8) * 2);
            ah[3] = *(const u32*)(AB + (gq + 8) * 272 + (kc + 8) * 2);
#pragma unroll
            for (int j = 0; j < 16; ++j) {
                const char* bh = sm + SW2H + ((j * 8 + gq) * 136 + kc) * 2;
                const char* bl = sm + SW2L + ((j * 8 + gq) * 136 + kc) * 2;
                u32 b0h = *(const u32*)bh, b1h = *(const u32*)(bh + 16);
                u32 b0l = *(const u32*)bl, b1l = *(const u32*)(bl + 16);
                mma16816(acc2[j], ah, b0h, b1h);
                mma16816(acc2[j], ah, b0l, b1l);
            }
        }

        // ---- epilogue B: silu -> ef (two 64-col chunks), column partials ----
        {
            float* ef = (float*)AB;
            int sA = e0 / 20;
            int bnd = 20 * (sA + 1) - e0;
            if (bnd > 16) bnd = 16;
#pragma unroll
            for (int half = 0; half < 2; ++half) {
                __syncwarp();
#pragma unroll
                for (int j = half * 8; j < half * 8 + 8; ++j) {
                    int c0 = j * 8 + 2 * tig;
                    float2 bb = *(const float2*)&b2[c0];
                    float2 v0, v1;
                    v0.x = siluf(acc2[j][0] + bb.x);
                    v0.y = siluf(acc2[j][1] + bb.y);
                    v1.x = siluf(acc2[j][2] + bb.x);
                    v1.y = siluf(acc2[j][3] + bb.y);
                    int cl = c0 - half * 64;
                    *(float2*)&ef[gq * 68 + cl] = v0;
                    *(float2*)&ef[(gq + 8) * 68 + cl] = v1;
                }
                __syncwarp();
                int cl = 2 * lane;
                float2 p0 = make_float2(0.f, 0.f), p1 = make_float2(0.f, 0.f);
#pragma unroll
                for (int r = 0; r < 16; ++r) {
                    float2 v = *(const float2*)&ef[r * 68 + cl];
                    if (r < bnd) { p0.x += v.x; p0.y += v.y; }
                    else { p1.x += v.x; p1.y += v.y; }
                }
                *(float2*)&part[(tt * 2) * 128 + half * 64 + cl] = p0;
                *(float2*)&part[(tt * 2 + 1) * 128 + half * 64 + cl] = p1;
            }
        }
        __syncwarp();
    }
    __syncthreads();

    // ---- combine partials -> scatter-mean ----
    for (int idx = tid; idx < 2560; idx += 512) {
        int s = idx >> 7, c = idx & 127;
        int t0 = (20 * s) >> 4, t1 = (20 * s + 19) >> 4;
        float a = 0.f;
        for (int t = t0; t <= t1; ++t) {
            int sA = (16 * t) / 20;
            int sB = (16 * t + 15) / 20;
            if (sA == s) a += part[t * 256 + c];
            else if (sB == s) a += part[t * 256 + 128 + c];
        }
        g_agg[g0 * 2560 + idx] = a * 0.05f;
    }
}

// ---------------- per-layer node MLP + residual ----------------
__global__ __launch_bounds__(128) void k_nodemlp(
    const float* __restrict__ nw1, const float* __restrict__ nb1,
    const float* __restrict__ nw2, const float* __restrict__ nb2)
{
    __shared__ __align__(16) float inT[256 * 20];
    __shared__ __align__(16) float nfT[128 * 20];
    int g = blockIdx.x, tid = threadIdx.x;
    for (int n = 0; n < 20; ++n) {
        inT[tid * 20 + n] = g_h[(g * 20 + n) * H_DIM + tid];
        inT[(128 + tid) * 20 + n] = g_agg[(g * 20 + n) * H_DIM + tid];
    }
    __syncthreads();
    float b1 = nb1[tid];
    u64 acc[10];
#pragma unroll
    for (int i = 0; i < 10; ++i) acc[i] = pack2(b1, b1);
#pragma unroll 4
    for (int k = 0; k < 256; ++k) {
        float w = nw1[k * H_DIM + tid];
        fma20p(acc, &inT[k * 20], pack2(w, w));
    }
#pragma unroll
    for (int i = 0; i < 5; ++i) {
        float a0, a1, a2, a3;
        unpack2(acc[2 * i], a0, a1);
        unpack2(acc[2 * i + 1], a2, a3);
        float4 v;
        v.x = siluf(a0); v.y = siluf(a1); v.z = siluf(a2); v.w = siluf(a3);
        ((float4*)&nfT[tid * 20])[i] = v;
    }
    __syncthreads();
    float b2 = nb2[tid];
    u64 acc2[10];
#pragma unroll
    for (int i = 0; i < 10; ++i) acc2[i] = pack2(b2, b2);
#pragma unroll 4
    for (int k = 0; k < 128; ++k) {
        float w = nw2[k * H_DIM + tid];
        fma20p(acc2, &nfT[k * 20], pack2(w, w));
    }
#pragma unroll
    for (int i = 0; i < 10; ++i) {
        float a0, a1;
        unpack2(acc2[i], a0, a1);
        g_h[(g * 20 + 2 * i) * H_DIM + tid] = inT[tid * 20 + 2 * i] + siluf(a0);
        g_h[(g * 20 + 2 * i + 1) * H_DIM + tid] = inT[tid * 20 + 2 * i + 1] + siluf(a1);
    }
}

// ---------------- output heads ----------------
__global__ __launch_bounds__(128) void k_final(
    const float* __restrict__ lattices, const float* __restrict__ coord_w,
    const float* __restrict__ lattice_w, float* __restrict__ out)
{
    __shared__ __align__(16) float hT[128 * 20];
    __shared__ float gf[128];
    __shared__ float pre[9];
    int g = blockIdx.x, tid = threadIdx.x;
    for (int n = 0; n < 20; ++n)
        hT[tid * 20 + n] = g_h[(g * 20 + n) * H_DIM + tid];
    __syncthreads();
    float s = 0.f;
#pragma unroll
    for (int n = 0; n < 20; ++n) s += hT[tid * 20 + n];
    gf[tid] = s * 0.05f;
    __syncthreads();
    if (tid < 9) {
        float acc = 0.f;
        for (int k = 0; k < 128; ++k) acc += gf[k] * lattice_w[k * 9 + tid];
        pre[tid] = acc;
    }
    __syncthreads();
    if (tid < 9) {
        int i = tid / 3, kk = tid % 3;
        float v = 0.f;
#pragma unroll
        for (int j = 0; j < 3; ++j)
            v += pre[i * 3 + j] * lattices[g * 9 + j * 3 + kk];
        out[g * 9 + tid] = v;
    }
    if (tid < 60) {
        int n = tid / 3, c = tid % 3;
        float acc = 0.f;
        for (int k = 0; k < 128; ++k) acc += hT[k * 20 + n] * coord_w[k * 3 + c];
        out[G_CNT * 9 + (g * 20 + n) * 3 + c] = acc;
    }
}

// ---------------- launch ----------------
extern "C" void kernel_launch(void* const* d_in, const int* in_sizes, int n_in,
                              void* d_out, int out_size) {
    const int*   atom_types = (const int*)d_in[0];
    const float* frac       = (const float*)d_in[1];
    const float* lattices   = (const float*)d_in[2];
    const float* t          = (const float*)d_in[3];
    const float* emb_table  = (const float*)d_in[7];
    const float* w_latent   = (const float*)d_in[8];
    const float* b_latent   = (const float*)d_in[9];
    const float* ew1        = (const float*)d_in[10];
    const float* eb1        = (const float*)d_in[11];
    const float* ew2        = (const float*)d_in[12];
    const float* eb2        = (const float*)d_in[13];
    const float* nw1        = (const float*)d_in[14];
    const float* nb1        = (const float*)d_in[15];
    const float* nw2        = (const float*)d_in[16];
    const float* nb2        = (const float*)d_in[17];
    const float* coord_w    = (const float*)d_in[18];
    const float* lattice_w  = (const float*)d_in[19];
    float* out = (float*)d_out;

    cudaFuncSetAttribute(k_edge_m, cudaFuncAttributeMaxDynamicSharedMemorySize, SM_TOT);

    k_latip<<<G_CNT, 32>>>(lattices);
    k_embed<<<G_CNT, 128>>>(atom_types, t, emb_table, w_latent, b_latent);
    k_dis<<<E_CNT / 128, 128>>>(frac);
    for (int i = 0; i < NLAYER; ++i) {
        k_nodeside<<<G_CNT, 128>>>(ew1 + i * 325 * 128, eb1 + i * 128);
        k_edge_m<<<G_CNT, 512, SM_TOT>>>(ew1 + i * 325 * 128,
                                         ew2 + i * 128 * 128, eb2 + i * 128);
        k_nodemlp<<<G_CNT, 128>>>(nw1 + i * 256 * 128, nb1 + i * 128,
                                  nw2 + i * 128 * 128, nb2 + i * 128);
    }
    k_final<<<G_CNT, 128>>>(lattices, coord_w, lattice_w, out);
}

// round 7
// speedup vs baseline: 3.3046x; 1.2526x over previous
#include <cuda_runtime.h>
#include <cuda_bf16.h>
#include <cuda_fp16.h>
#include <math.h>
#include <stdint.h>

#define G_CNT 1024
#define A_CNT 20
#define N_CNT (G_CNT * A_CNT)          // 20480
#define E_CNT (G_CNT * A_CNT * A_CNT)  // 409600
#define H_DIM 128
#define NLAYER 4

typedef unsigned long long u64;
typedef unsigned int u32;
typedef unsigned short u16;

// ---------------- scratch (device globals) ----------------
__device__ float g_h[N_CNT * H_DIM];
__device__ float g_hs[N_CNT * H_DIM];
__device__ float g_hd[N_CNT * H_DIM];
__device__ float g_agg[N_CNT * H_DIM];
__device__ float g_latip[G_CNT * 9];
__device__ float g_latterm[G_CNT * H_DIM];
__device__ u16 g_disH[(size_t)E_CNT * 64];       // dis fp16 [edge][64]
// fp16 weights, consumer-ready K-major [n][k]
__device__ u16 g_w1d[NLAYER * 128 * 64];
__device__ u16 g_w1n[NLAYER * 256 * 128];
__device__ u16 g_w2[NLAYER * 128 * 128];
__device__ u16 g_nw1[NLAYER * 128 * 256];
__device__ u16 g_nw2[NLAYER * 128 * 128];

__device__ __forceinline__ float siluf(float x) {
    return __fdividef(x, 1.0f + __expf(-x));
}
__device__ __forceinline__ u16 h_rn(float x) {
    return __half_as_ushort(__float2half_rn(x));
}
__device__ __forceinline__ u32 pack_h2(float a, float b) {
    __half2 hh = __floats2half2_rn(a, b);
    return *(u32*)&hh;
}

__device__ __forceinline__ void mma_f16(float c[4], const u32 a[4], u32 b0, u32 b1) {
    asm volatile(
        "mma.sync.aligned.m16n8k16.row.col.f32.f16.f16.f32 "
        "{%0,%1,%2,%3}, {%4,%5,%6,%7}, {%8,%9}, {%0,%1,%2,%3};"
        : "+f"(c[0]), "+f"(c[1]), "+f"(c[2]), "+f"(c[3])
        : "r"(a[0]), "r"(a[1]), "r"(a[2]), "r"(a[3]), "r"(b0), "r"(b1));
}

// fp32x2 packed helpers (scalar kernels)
__device__ __forceinline__ u64 pack2(float x, float y) {
    u64 r; asm("mov.b64 %0, {%1, %2};" : "=l"(r) : "f"(x), "f"(y)); return r;
}
__device__ __forceinline__ void unpack2(u64 v, float& x, float& y) {
    asm("mov.b64 {%0, %1}, %2;" : "=f"(x), "=f"(y) : "l"(v));
}
__device__ __forceinline__ void ffma2(u64& d, u64 a, u64 b) {
    asm("fma.rn.f32x2 %0, %1, %2, %0;" : "+l"(d) : "l"(a), "l"(b));
}
__device__ __forceinline__ void fma20p(u64 acc[10], const float* __restrict__ a, u64 w) {
#pragma unroll
    for (int q = 0; q < 5; ++q) {
        ulonglong2 v = reinterpret_cast<const ulonglong2*>(a)[q];
        ffma2(acc[2 * q], v.x, w);
        ffma2(acc[2 * q + 1], v.y, w);
    }
}

// ---------------- weight prep: fp32 -> fp16 K-major, once ----------------
__global__ __launch_bounds__(256) void k_prep(
    const float* __restrict__ ew1, const float* __restrict__ ew2,
    const float* __restrict__ nw1, const float* __restrict__ nw2)
{
    int i = blockIdx.x * 256 + threadIdx.x;
    if (i >= NLAYER * 106496) return;
    int L = i / 106496, j = i % 106496;
    const float* e1 = ew1 + L * 325 * 128;
    const float* e2 = ew2 + L * 128 * 128;
    const float* n1 = nw1 + L * 256 * 128;
    const float* n2 = nw2 + L * 128 * 128;
    if (j < 8192) {                       // w1d [n=128][k=64], pad k>=60
        int n = j >> 6, k = j & 63;
        float v = (k < 60) ? e1[(265 + k) * 128 + n] : 0.f;
        g_w1d[L * 8192 + j] = h_rn(v);
    } else if (j < 40960) {               // w1n [n=256][k=128]
        int jj = j - 8192;
        int n = jj >> 7, k = jj & 127;
        float v = (n < 128) ? e1[k * 128 + n] : e1[(128 + k) * 128 + (n - 128)];
        g_w1n[L * 32768 + jj] = h_rn(v);
    } else if (j < 57344) {               // w2 [n=128][k=128]
        int jj = j - 40960;
        int n = jj >> 7, k = jj & 127;
        g_w2[L * 16384 + jj] = h_rn(e2[k * 128 + n]);
    } else if (j < 90112) {               // nw1 [n=128][k=256]
        int jj = j - 57344;
        int n = jj >> 8, k = jj & 255;
        g_nw1[L * 32768 + jj] = h_rn(n1[k * 128 + n]);
    } else {                              // nw2 [n=128][k=128]
        int jj = j - 90112;
        int n = jj >> 7, k = jj & 127;
        g_nw2[L * 16384 + jj] = h_rn(n2[k * 128 + n]);
    }
}

// ---------------- lat_ip = L @ L^T ----------------
__global__ void k_latip(const float* __restrict__ lattices) {
    int g = blockIdx.x, tid = threadIdx.x;
    if (tid < 9) {
        int i = tid / 3, k = tid % 3;
        float s = 0.f;
#pragma unroll
        for (int j = 0; j < 3; ++j)
            s += lattices[g * 9 + i * 3 + j] * lattices[g * 9 + k * 3 + j];
        g_latip[g * 9 + tid] = s;
    }
}

// ---------------- dis embedding -> fp16, [e][64] ----------------
__global__ __launch_bounds__(128) void k_dis(const float* __restrict__ fc) {
    __shared__ u32 hiS[128 * 32];
    int tid = threadIdx.x;
    size_t e0 = (size_t)blockIdx.x * 128;
    int e = (int)e0 + tid;
    int g = e / 400, r = e % 400;
    int src = g * 20 + r / 20;
    int dst = g * 20 + r % 20;
    u16* hrow = (u16*)hiS + tid * 64;
#pragma unroll
    for (int c = 0; c < 3; ++c) {
        float d = fc[dst * 3 + c] - fc[src * 3 + c];
        d -= floorf(d);
        float s1, c1;
        sincospif(2.0f * d, &s1, &c1);
        float s = 0.f, co = 1.f;
        hrow[c * 10] = 0;
        hrow[30 + c * 10] = h_rn(1.f);
#pragma unroll
        for (int f = 1; f < 10; ++f) {
            float ns = s * c1 + co * s1;
            float nc = co * c1 - s * s1;
            s = ns; co = nc;
            hrow[c * 10 + f] = h_rn(s);
            hrow[30 + c * 10 + f] = h_rn(co);
        }
    }
#pragma unroll
    for (int k = 60; k < 64; ++k) hrow[k] = 0;
    __syncthreads();
    u32* gh = (u32*)g_disH + e0 * 32;
    for (int i = tid; i < 4096; i += 128) gh[i] = hiS[i];
}

// ---------------- node embedding + latent conditioning (scalar fp32) ------
__global__ __launch_bounds__(128) void k_embed(
    const int* __restrict__ atom_types, const float* __restrict__ t,
    const float* __restrict__ emb_table, const float* __restrict__ w_latent,
    const float* __restrict__ b_latent)
{
    __shared__ __align__(16) float inT[384 * 20];
    __shared__ int at[20];
    int g = blockIdx.x, tid = threadIdx.x;
    if (tid < 20) at[tid] = atom_types[g * 20 + tid];
    __syncthreads();
    for (int n = 0; n < 20; ++n)
        inT[tid * 20 + n] = emb_table[at[n] * H_DIM + tid];
    for (int k = tid; k < 256; k += 128) {
        float v = t[g * 256 + k];
#pragma unroll
        for (int n = 0; n < 20; ++n) inT[(128 + k) * 20 + n] = v;
    }
    __syncthreads();
    float b = b_latent[tid];
    u64 acc[10];
#pragma unroll
    for (int i = 0; i < 10; ++i) acc[i] = pack2(b, b);
#pragma unroll 4
    for (int k = 0; k < 384; ++k) {
        float w = w_latent[k * H_DIM + tid];
        fma20p(acc, &inT[k * 20], pack2(w, w));
    }
#pragma unroll
    for (int i = 0; i < 10; ++i) {
        float a0, a1;
        unpack2(acc[i], a0, a1);
        g_h[(g * 20 + 2 * i) * H_DIM + tid] = a0;
        g_h[(g * 20 + 2 * i + 1) * H_DIM + tid] = a1;
    }
}

// ---------------- tensor nodeside: hs|hd = h @ W1[:256] ----------------
// block = graph, 256 threads = 8 warps. A = h fp16 [32 rows pad][k=128],
// B = g_w1n [n=256][k=128]. Warp: m-tile = w&1, n-tiles (w>>1)*8 .. +8.
#define NSA 0                      // A 32*272 = 8704
#define NSB 8704                   // B 256*272 = 69632
#define NS_TOT 78336

__global__ __launch_bounds__(256, 2) void k_nodeside_t(
    int L, const float* __restrict__ ew1, const float* __restrict__ eb1)
{
    extern __shared__ char sm[];
    int g = blockIdx.x, tid = threadIdx.x;
    int w = tid >> 5, lane = tid & 31;
    int gq = lane >> 2, tig = lane & 3;

    // lat term (independent)
    if (tid < 128) {
        float lt = eb1[tid];
#pragma unroll
        for (int j = 0; j < 9; ++j)
            lt += g_latip[g * 9 + j] * ew1[(256 + j) * H_DIM + tid];
        g_latterm[g * H_DIM + tid] = lt;
    }
    // stage A: h -> fp16 [r][stride 136 halves]
    for (int idx = tid; idx < 1280; idx += 256) {
        int r = idx >> 6, c2 = idx & 63;
        const float* src = g_h + g * 2560 + r * 128 + c2 * 2;
        *(u32*)(sm + NSA + r * 272 + c2 * 4) = pack_h2(src[0], src[1]);
    }
    for (int idx = tid; idx < 768; idx += 256) {   // zero rows 20..31
        int r = 20 + (idx >> 6), c2 = idx & 63;
        *(u32*)(sm + NSA + r * 272 + c2 * 4) = 0;
    }
    // stage B
    {
        const u32* src = (const u32*)(g_w1n + L * 32768);
        for (int idx = tid; idx < 16384; idx += 256) {
            int n = idx >> 6, k2 = idx & 63;
            *(u32*)(sm + NSB + n * 272 + k2 * 4) = src[idx];
        }
    }
    __syncthreads();

    int mt = w & 1;
    int nb = (w >> 1) * 8;
    float acc[8][4];
#pragma unroll
    for (int j = 0; j < 8; ++j)
        acc[j][0] = acc[j][1] = acc[j][2] = acc[j][3] = 0.f;
#pragma unroll
    for (int ks = 0; ks < 8; ++ks) {
        int kc = ks * 16 + 2 * tig;
        u32 ah[4];
        const char* Ab = sm + NSA + (mt * 16) * 272;
        ah[0] = *(const u32*)(Ab + gq * 272 + kc * 2);
        ah[1] = *(const u32*)(Ab + (gq + 8) * 272 + kc * 2);
        ah[2] = *(const u32*)(Ab + gq * 272 + (kc + 8) * 2);
        ah[3] = *(const u32*)(Ab + (gq + 8) * 272 + (kc + 8) * 2);
#pragma unroll
        for (int j = 0; j < 8; ++j) {
            const char* bh = sm + NSB + ((nb + j) * 8 + gq) * 272 + kc * 2;
            mma_f16(acc[j], ah, *(const u32*)bh, *(const u32*)(bh + 16));
        }
    }
    // store
    int rowA = mt * 16 + gq, rowB = rowA + 8;
#pragma unroll
    for (int j = 0; j < 8; ++j) {
        int n = (nb + j) * 8 + 2 * tig;
        float* dA = (n < 128) ? (g_hs + g * 2560 + rowA * 128 + n)
                              : (g_hd + g * 2560 + rowA * 128 + n - 128);
        float* dB = (n < 128) ? (g_hs + g * 2560 + rowB * 128 + n)
                              : (g_hd + g * 2560 + rowB * 128 + n - 128);
        if (rowA < 20) *(float2*)dA = make_float2(acc[j][0], acc[j][1]);
        if (rowB < 20) *(float2*)dB = make_float2(acc[j][2], acc[j][3]);
    }
}

// ---------------- tensor (mma.sync fp16) edge kernel ----------------
// block = 1 graph, 512 threads = 16 warps; 400 edges = 25 tiles x 16 rows.
#define SW1 0           // W1d [128][72 halves] 18432
#define SW2 18432       // W2 [128][136] 34816
#define SAW 53248       // 16 warps x 4352
#define SHS 122880
#define SHD 133120
#define SLAT 143360
#define SB2 143872
#define SPART 144384    // [25][2][128] f32 = 25600
#define SM_TOT 169984

__global__ __launch_bounds__(512, 1) void k_edge_m(
    int L, const float* __restrict__ eb2)
{
    extern __shared__ char sm[];
    int tid = threadIdx.x, g0 = blockIdx.x;
    int w = tid >> 5, lane = tid & 31;
    int gq = lane >> 2, tig = lane & 3;

    // ---- stage fp16 weights (plain u32 copies) ----
    {
        const u32* src = (const u32*)(g_w1d + L * 8192);
        for (int idx = tid; idx < 4096; idx += 512) {
            int n = idx >> 5, k2 = idx & 31;
            *(u32*)(sm + SW1 + n * 144 + k2 * 4) = src[idx];
        }
    }
    {
        const u32* src = (const u32*)(g_w2 + L * 16384);
        for (int idx = tid; idx < 8192; idx += 512) {
            int n = idx >> 6, k2 = idx & 63;
            *(u32*)(sm + SW2 + n * 272 + k2 * 4) = src[idx];
        }
    }
    float* hs = (float*)(sm + SHS);
    float* hd = (float*)(sm + SHD);
    for (int i = tid; i < 2560; i += 512) {
        hs[i] = g_hs[g0 * 2560 + i];
        hd[i] = g_hd[g0 * 2560 + i];
    }
    if (tid < 128) {
        ((float*)(sm + SLAT))[tid] = g_latterm[g0 * H_DIM + tid];
        ((float*)(sm + SB2))[tid] = eb2[tid];
    }
    __syncthreads();

    char* AB = sm + SAW + w * 4352;
    float* lat = (float*)(sm + SLAT);
    float* b2 = (float*)(sm + SB2);
    float* part = (float*)(sm + SPART);

    for (int tt = w; tt < 25; tt += 16) {
        int e0 = tt * 16;
        // ---- stage dis tile [16][64] fp16, row stride 144B ----
        {
            const uint4* sH = (const uint4*)(g_disH + ((size_t)g0 * 400 + e0) * 64);
#pragma unroll
            for (int q = 0; q < 4; ++q) {
                int idx = lane + q * 32;
                int row = idx >> 3, seg = idx & 7;
                *(uint4*)(AB + row * 144 + seg * 16) = sH[row * 8 + seg];
            }
        }
        __syncwarp();

        // ---- GEMM1: dis[16,64] @ W1d[64,128] ----
        float acc[16][4];
#pragma unroll
        for (int j = 0; j < 16; ++j)
            acc[j][0] = acc[j][1] = acc[j][2] = acc[j][3] = 0.f;
#pragma unroll
        for (int ks = 0; ks < 4; ++ks) {
            int kc = ks * 16 + 2 * tig;
            u32 ah[4];
            ah[0] = *(const u32*)(AB + gq * 144 + kc * 2);
            ah[1] = *(const u32*)(AB + (gq + 8) * 144 + kc * 2);
            ah[2] = *(const u32*)(AB + gq * 144 + (kc + 8) * 2);
            ah[3] = *(const u32*)(AB + (gq + 8) * 144 + (kc + 8) * 2);
#pragma unroll
            for (int j = 0; j < 16; ++j) {
                const char* bh = sm + SW1 + ((j * 8 + gq) * 72 + kc) * 2;
                mma_f16(acc[j], ah, *(const u32*)bh, *(const u32*)(bh + 16));
            }
        }
        __syncwarp();

        // ---- epilogue A: + hs[src] + hd[dst] + lat, silu, fp16 -> A2 ----
        {
            int eA = e0 + gq, eB = e0 + gq + 8;
            int srcA = eA / 20, dstA = eA - srcA * 20;
            int srcB = eB / 20, dstB = eB - srcB * 20;
#pragma unroll
            for (int j = 0; j < 16; ++j) {
                int c0 = j * 8 + 2 * tig;
                float2 la = *(const float2*)&lat[c0];
                float2 hsA = *(const float2*)&hs[srcA * 128 + c0];
                float2 hdA = *(const float2*)&hd[dstA * 128 + c0];
                float2 hsB = *(const float2*)&hs[srcB * 128 + c0];
                float2 hdB = *(const float2*)&hd[dstB * 128 + c0];
                float x0 = siluf(acc[j][0] + hsA.x + hdA.x + la.x);
                float x1 = siluf(acc[j][1] + hsA.y + hdA.y + la.y);
                float x2 = siluf(acc[j][2] + hsB.x + hdB.x + la.x);
                float x3 = siluf(acc[j][3] + hsB.y + hdB.y + la.y);
                *(u32*)(AB + gq * 272 + c0 * 2) = pack_h2(x0, x1);
                *(u32*)(AB + (gq + 8) * 272 + c0 * 2) = pack_h2(x2, x3);
            }
        }
        __syncwarp();

        // ---- GEMM2: ef[16,128] @ W2[128,128] ----
        float acc2[16][4];
#pragma unroll
        for (int j = 0; j < 16; ++j)
            acc2[j][0] = acc2[j][1] = acc2[j][2] = acc2[j][3] = 0.f;
#pragma unroll
        for (int ks = 0; ks < 8; ++ks) {
            int kc = ks * 16 + 2 * tig;
            u32 ah[4];
            ah[0] = *(const u32*)(AB + gq * 272 + kc * 2);
            ah[1] = *(const u32*)(AB + (gq + 8) * 272 + kc * 2);
            ah[2] = *(const u32*)(AB + gq * 272 + (kc + 8) * 2);
            ah[3] = *(const u32*)(AB + (gq + 8) * 272 + (kc + 8) * 2);
#pragma unroll
            for (int j = 0; j < 16; ++j) {
                const char* bh = sm + SW2 + ((j * 8 + gq) * 136 + kc) * 2;
                mma_f16(acc2[j], ah, *(const u32*)bh, *(const u32*)(bh + 16));
            }
        }

        // ---- epilogue B: silu -> ef (two 64-col chunks), column partials ----
        {
            float* ef = (float*)AB;
            int sA = e0 / 20;
            int bnd = 20 * (sA + 1) - e0;
            if (bnd > 16) bnd = 16;
#pragma unroll
            for (int half = 0; half < 2; ++half) {
                __syncwarp();
#pragma unroll
                for (int j = half * 8; j < half * 8 + 8; ++j) {
                    int c0 = j * 8 + 2 * tig;
                    float2 bb = *(const float2*)&b2[c0];
                    float2 v0, v1;
                    v0.x = siluf(acc2[j][0] + bb.x);
                    v0.y = siluf(acc2[j][1] + bb.y);
                    v1.x = siluf(acc2[j][2] + bb.x);
                    v1.y = siluf(acc2[j][3] + bb.y);
                    int cl = c0 - half * 64;
                    *(float2*)&ef[gq * 68 + cl] = v0;
                    *(float2*)&ef[(gq + 8) * 68 + cl] = v1;
                }
                __syncwarp();
                int cl = 2 * lane;
                float2 p0 = make_float2(0.f, 0.f), p1 = make_float2(0.f, 0.f);
#pragma unroll
                for (int r = 0; r < 16; ++r) {
                    float2 v = *(const float2*)&ef[r * 68 + cl];
                    if (r < bnd) { p0.x += v.x; p0.y += v.y; }
                    else { p1.x += v.x; p1.y += v.y; }
                }
                *(float2*)&part[(tt * 2) * 128 + half * 64 + cl] = p0;
                *(float2*)&part[(tt * 2 + 1) * 128 + half * 64 + cl] = p1;
            }
        }
        __syncwarp();
    }
    __syncthreads();

    // ---- combine partials -> scatter-mean ----
    for (int idx = tid; idx < 2560; idx += 512) {
        int s = idx >> 7, c = idx & 127;
        int t0 = (20 * s) >> 4, t1 = (20 * s + 19) >> 4;
        float a = 0.f;
        for (int t = t0; t <= t1; ++t) {
            int sA = (16 * t) / 20;
            int sB = (16 * t + 15) / 20;
            if (sA == s) a += part[t * 256 + c];
            else if (sB == s) a += part[t * 256 + 128 + c];
        }
        g_agg[g0 * 2560 + idx] = a * 0.05f;
    }
}

// ---------------- tensor node MLP + residual ----------------
// A1 = [h|agg] [32 pad][256] fp16; B1 = g_nw1 [128][256]; A2 [32][128];
// B2 = g_nw2 [128][128].
#define NMA1 0          // 32*528 = 16896
#define NMB1 16896      // 128*528 = 67584 -> 84480
#define NMA2 84480      // 32*272 = 8704  -> 93184
#define NMB2 93184      // 128*272 = 34816 -> 128000
#define NM_TOT 128000

__global__ __launch_bounds__(256, 1) void k_nodemlp_t(
    int L, const float* __restrict__ nb1, const float* __restrict__ nb2)
{
    extern __shared__ char sm[];
    int g = blockIdx.x, tid = threadIdx.x;
    int w = tid >> 5, lane = tid & 31;
    int gq = lane >> 2, tig = lane & 3;

    // stage A1 rows 0-19, zero rows 20-31
    for (int idx = tid; idx < 2560; idx += 256) {
        int r = idx >> 7, c2 = idx & 127;
        float a0, a1;
        if (c2 < 64) {
            const float* s = g_h + g * 2560 + r * 128 + c2 * 2;
            a0 = s[0]; a1 = s[1];
        } else {
            const float* s = g_agg + g * 2560 + r * 128 + (c2 - 64) * 2;
            a0 = s[0]; a1 = s[1];
        }
        *(u32*)(sm + NMA1 + r * 528 + c2 * 4) = pack_h2(a0, a1);
    }
    for (int idx = tid; idx < 1536; idx += 256) {
        int r = 20 + (idx >> 7), c2 = idx & 127;
        *(u32*)(sm + NMA1 + r * 528 + c2 * 4) = 0;
    }
    {
        const u32* src = (const u32*)(g_nw1 + L * 32768);
        for (int idx = tid; idx < 16384; idx += 256) {
            int n = idx >> 7, k2 = idx & 127;
            *(u32*)(sm + NMB1 + n * 528 + k2 * 4) = src[idx];
        }
        const u32* src2 = (const u32*)(g_nw2 + L * 16384);
        for (int idx = tid; idx < 8192; idx += 256) {
            int n = idx >> 6, k2 = idx & 63;
            *(u32*)(sm + NMB2 + n * 272 + k2 * 4) = src2[idx];
        }
    }
    __syncthreads();

    int mt = w & 1;
    int nb = (w >> 1) * 4;
    // ---- GEMM1: [32,256] @ [256,128] -> nf ----
    float acc[4][4];
#pragma unroll
    for (int j = 0; j < 4; ++j)
        acc[j][0] = acc[j][1] = acc[j][2] = acc[j][3] = 0.f;
#pragma unroll
    for (int ks = 0; ks < 16; ++ks) {
        int kc = ks * 16 + 2 * tig;
        u32 ah[4];
        const char* Ab = sm + NMA1 + (mt * 16) * 528;
        ah[0] = *(const u32*)(Ab + gq * 528 + kc * 2);
        ah[1] = *(const u32*)(Ab + (gq + 8) * 528 + kc * 2);
        ah[2] = *(const u32*)(Ab + gq * 528 + (kc + 8) * 2);
        ah[3] = *(const u32*)(Ab + (gq + 8) * 528 + (kc + 8) * 2);
#pragma unroll
        for (int j = 0; j < 4; ++j) {
            const char* bh = sm + NMB1 + ((nb + j) * 8 + gq) * 528 + kc * 2;
            mma_f16(acc[j], ah, *(const u32*)bh, *(const u32*)(bh + 16));
        }
    }
    // epilogue 1: silu -> A2 fp16
    {
        int rA = mt * 16 + gq;
#pragma unroll
        for (int j = 0; j < 4; ++j) {
            int c0 = (nb + j) * 8 + 2 * tig;
            float bb0 = __ldg(nb1 + c0), bb1 = __ldg(nb1 + c0 + 1);
            *(u32*)(sm + NMA2 + rA * 272 + c0 * 2) =
                pack_h2(siluf(acc[j][0] + bb0), siluf(acc[j][1] + bb1));
            *(u32*)(sm + NMA2 + (rA + 8) * 272 + c0 * 2) =
                pack_h2(siluf(acc[j][2] + bb0), siluf(acc[j][3] + bb1));
        }
    }
    __syncthreads();

    // ---- GEMM2: [32,128] @ [128,128] ----
    float acc2[4][4];
#pragma unroll
    for (int j = 0; j < 4; ++j)
        acc2[j][0] = acc2[j][1] = acc2[j][2] = acc2[j][3] = 0.f;
#pragma unroll
    for (int ks = 0; ks < 8; ++ks) {
        int kc = ks * 16 + 2 * tig;
        u32 ah[4];
        const char* Ab = sm + NMA2 + (mt * 16) * 272;
        ah[0] = *(const u32*)(Ab + gq * 272 + kc * 2);
        ah[1] = *(const u32*)(Ab + (gq + 8) * 272 + kc * 2);
        ah[2] = *(const u32*)(Ab + gq * 272 + (kc + 8) * 2);
        ah[3] = *(const u32*)(Ab + (gq + 8) * 272 + (kc + 8) * 2);
#pragma unroll
        for (int j = 0; j < 4; ++j) {
            const char* bh = sm + NMB2 + ((nb + j) * 8 + gq) * 136 * 2 + kc * 2;
            mma_f16(acc2[j], ah, *(const u32*)bh, *(const u32*)(bh + 16));
        }
    }
    // epilogue 2: h += silu(acc2 + nb2)
    {
        int rA = mt * 16 + gq, rB = rA + 8;
#pragma unroll
        for (int j = 0; j < 4; ++j) {
            int c0 = (nb + j) * 8 + 2 * tig;
            float bb0 = __ldg(nb2 + c0), bb1 = __ldg(nb2 + c0 + 1);
            if (rA < 20) {
                float* d = g_h + g * 2560 + rA * 128 + c0;
                float2 o = *(float2*)d;
                o.x += siluf(acc2[j][0] + bb0);
                o.y += siluf(acc2[j][1] + bb1);
                *(float2*)d = o;
            }
            if (rB < 20) {
                float* d = g_h + g * 2560 + rB * 128 + c0;
                float2 o = *(float2*)d;
                o.x += siluf(acc2[j][2] + bb0);
                o.y += siluf(acc2[j][3] + bb1);
                *(float2*)d = o;
            }
        }
    }
}

// ---------------- output heads ----------------
__global__ __launch_bounds__(128) void k_final(
    const float* __restrict__ lattices, const float* __restrict__ coord_w,
    const float* __restrict__ lattice_w, float* __restrict__ out)
{
    __shared__ __align__(16) float hT[128 * 20];
    __shared__ float gf[128];
    __shared__ float pre[9];
    int g = blockIdx.x, tid = threadIdx.x;
    for (int n = 0; n < 20; ++n)
        hT[tid * 20 + n] = g_h[(g * 20 + n) * H_DIM + tid];
    __syncthreads();
    float s = 0.f;
#pragma unroll
    for (int n = 0; n < 20; ++n) s += hT[tid * 20 + n];
    gf[tid] = s * 0.05f;
    __syncthreads();
    if (tid < 9) {
        float acc = 0.f;
        for (int k = 0; k < 128; ++k) acc += gf[k] * lattice_w[k * 9 + tid];
        pre[tid] = acc;
    }
    __syncthreads();
    if (tid < 9) {
        int i = tid / 3, kk = tid % 3;
        float v = 0.f;
#pragma unroll
        for (int j = 0; j < 3; ++j)
            v += pre[i * 3 + j] * lattices[g * 9 + j * 3 + kk];
        out[g * 9 + tid] = v;
    }
    if (tid < 60) {
        int n = tid / 3, c = tid % 3;
        float acc = 0.f;
        for (int k = 0; k < 128; ++k) acc += hT[k * 20 + n] * coord_w[k * 3 + c];
        out[G_CNT * 9 + (g * 20 + n) * 3 + c] = acc;
    }
}

// ---------------- launch ----------------
extern "C" void kernel_launch(void* const* d_in, const int* in_sizes, int n_in,
                              void* d_out, int out_size) {
    const int*   atom_types = (const int*)d_in[0];
    const float* frac       = (const float*)d_in[1];
    const float* lattices   = (const float*)d_in[2];
    const float* t          = (const float*)d_in[3];
    const float* emb_table  = (const float*)d_in[7];
    const float* w_latent   = (const float*)d_in[8];
    const float* b_latent   = (const float*)d_in[9];
    const float* ew1        = (const float*)d_in[10];
    const float* eb1        = (const float*)d_in[11];
    const float* ew2        = (const float*)d_in[12];
    const float* eb2        = (const float*)d_in[13];
    const float* nw1        = (const float*)d_in[14];
    const float* nb1        = (const float*)d_in[15];
    const float* nw2        = (const float*)d_in[16];
    const float* nb2        = (const float*)d_in[17];
    const float* coord_w    = (const float*)d_in[18];
    const float* lattice_w  = (const float*)d_in[19];
    float* out = (float*)d_out;

    cudaFuncSetAttribute(k_edge_m, cudaFuncAttributeMaxDynamicSharedMemorySize, SM_TOT);
    cudaFuncSetAttribute(k_nodemlp_t, cudaFuncAttributeMaxDynamicSharedMemorySize, NM_TOT);
    cudaFuncSetAttribute(k_nodeside_t, cudaFuncAttributeMaxDynamicSharedMemorySize, NS_TOT);

    k_prep<<<(NLAYER * 106496 + 255) / 256, 256>>>(ew1, ew2, nw1, nw2);
    k_latip<<<G_CNT, 32>>>(lattices);
    k_embed<<<G_CNT, 128>>>(atom_types, t, emb_table, w_latent, b_latent);
    k_dis<<<E_CNT / 128, 128>>>(frac);
    for (int i = 0; i < NLAYER; ++i) {
        k_nodeside_t<<<G_CNT, 256, NS_TOT>>>(i, ew1 + i * 325 * 128, eb1 + i * 128);
        k_edge_m<<<G_CNT, 512, SM_TOT>>>(i, eb2 + i * 128);
        k_nodemlp_t<<<G_CNT, 256, NM_TOT>>>(i, nb1 + i * 128, nb2 + i * 128);
    }
    k_final<<<G_CNT, 128>>>(lattices, coord_w, lattice_w, out);
}